// round 1
// baseline (speedup 1.0000x reference)
#include <cuda_runtime.h>

#define NN 100000
#define NE_MAX 3400000
#define F_IN   512
#define F_HID  256
#define F_CLS  64
#define F_PROJ 128

// ---------------- scratch (static device globals; no allocation) ----------------
__device__ float g_XW1[(size_t)NN * F_HID];   // x @ W1
__device__ float g_h  [(size_t)NN * F_HID];   // relu(spmm + b1)
__device__ float g_HW2[(size_t)NN * F_CLS];   // h @ W2
__device__ float g_z  [(size_t)NN * F_CLS];   // spmm + b2
__device__ int   g_counts[NN];
__device__ int   g_rowptr[NN + 1];
__device__ int   g_cursor[NN];
__device__ int   g_colsorted[NE_MAX];
__device__ float g_valsorted[NE_MAX];

// ---------------- edge bucketing (counting sort by destination row) -------------
__global__ void k_zero_counts(int n) {
    int i = blockIdx.x * blockDim.x + threadIdx.x;
    if (i < n) g_counts[i] = 0;
}

__global__ void k_hist(const int* __restrict__ rows, int E) {
    int e = blockIdx.x * blockDim.x + threadIdx.x;
    if (e < E) atomicAdd(&g_counts[rows[e]], 1);
}

// single-block exclusive scan over counts -> rowptr (+ cursor copy)
__global__ void k_scan(int n) {
    __shared__ int part[1024];
    int tid = threadIdx.x;
    int per = (n + 1023) >> 10;
    int st = tid * per;
    int en = st + per; if (en > n) en = n;
    int s = 0;
    for (int i = st; i < en; i++) s += g_counts[i];
    part[tid] = s;
    __syncthreads();
    #pragma unroll
    for (int off = 1; off < 1024; off <<= 1) {
        int v = (tid >= off) ? part[tid - off] : 0;
        __syncthreads();
        part[tid] += v;
        __syncthreads();
    }
    int base = (tid == 0) ? 0 : part[tid - 1];
    for (int i = st; i < en; i++) {
        int c = g_counts[i];
        g_rowptr[i] = base;
        g_cursor[i] = base;
        base += c;
    }
    if (tid == 1023) g_rowptr[n] = part[1023];
}

__global__ void k_scatter(const int* __restrict__ rows, const int* __restrict__ cols,
                          const float* __restrict__ vals, int E) {
    int e = blockIdx.x * blockDim.x + threadIdx.x;
    if (e < E) {
        int r = rows[e];
        int p = atomicAdd(&g_cursor[r], 1);
        g_colsorted[p] = cols[e];
        g_valsorted[p] = vals[e];
    }
}

// ---------------- SGEMM: C[M,N] = op(A)[M,K] @ B[K,N] (+bias) -------------------
// BM x BN block tile, TM x TN per-thread register tile, vectorized float4 paths.
template<int BM, int BN, int BK, int TM, int TN, bool RELU_A, bool ADD_BIAS>
__global__ void sgemm(const float* __restrict__ A, const float* __restrict__ B,
                      const float* __restrict__ bias, float* __restrict__ C,
                      int M, int N, int K) {
    constexpr int NT = (BM / TM) * (BN / TN);
    __shared__ float As[BK][BM];
    __shared__ float Bs[BK][BN];

    const int tid = threadIdx.x;
    const int tx = tid / (BN / TN);   // row group
    const int ty = tid % (BN / TN);   // col group
    const int m0 = blockIdx.y * BM;
    const int n0 = blockIdx.x * BN;

    float acc[TM][TN];
    #pragma unroll
    for (int i = 0; i < TM; i++)
        #pragma unroll
        for (int j = 0; j < TN; j++) acc[i][j] = 0.f;

    for (int k0 = 0; k0 < K; k0 += BK) {
        // load A tile (transposed into smem: As[k][m])
        #pragma unroll
        for (int i = tid; i < BM * BK / 4; i += NT) {
            int r  = i / (BK / 4);
            int ks = i % (BK / 4);
            float4 v;
            if (m0 + r < M)
                v = *reinterpret_cast<const float4*>(A + (size_t)(m0 + r) * K + k0 + ks * 4);
            else
                v = make_float4(0.f, 0.f, 0.f, 0.f);
            if (RELU_A) {
                v.x = fmaxf(v.x, 0.f); v.y = fmaxf(v.y, 0.f);
                v.z = fmaxf(v.z, 0.f); v.w = fmaxf(v.w, 0.f);
            }
            As[ks * 4 + 0][r] = v.x;
            As[ks * 4 + 1][r] = v.y;
            As[ks * 4 + 2][r] = v.z;
            As[ks * 4 + 3][r] = v.w;
        }
        // load B tile
        #pragma unroll
        for (int i = tid; i < BK * BN / 4; i += NT) {
            int r  = i / (BN / 4);
            int cs = i % (BN / 4);
            *reinterpret_cast<float4*>(&Bs[r][cs * 4]) =
                *reinterpret_cast<const float4*>(B + (size_t)(k0 + r) * N + n0 + cs * 4);
        }
        __syncthreads();

        #pragma unroll
        for (int k = 0; k < BK; k++) {
            float a[TM], b[TN];
            #pragma unroll
            for (int i = 0; i < TM; i += 4) {
                float4 v = *reinterpret_cast<const float4*>(&As[k][tx * TM + i]);
                a[i] = v.x; a[i + 1] = v.y; a[i + 2] = v.z; a[i + 3] = v.w;
            }
            #pragma unroll
            for (int j = 0; j < TN; j += 4) {
                float4 v = *reinterpret_cast<const float4*>(&Bs[k][ty * TN + j]);
                b[j] = v.x; b[j + 1] = v.y; b[j + 2] = v.z; b[j + 3] = v.w;
            }
            #pragma unroll
            for (int i = 0; i < TM; i++)
                #pragma unroll
                for (int j = 0; j < TN; j++)
                    acc[i][j] += a[i] * b[j];
        }
        __syncthreads();
    }

    #pragma unroll
    for (int i = 0; i < TM; i++) {
        int r = m0 + tx * TM + i;
        if (r < M) {
            #pragma unroll
            for (int j = 0; j < TN; j += 4) {
                float4 v;
                v.x = acc[i][j];     v.y = acc[i][j + 1];
                v.z = acc[i][j + 2]; v.w = acc[i][j + 3];
                if (ADD_BIAS) {
                    float4 bv = *reinterpret_cast<const float4*>(bias + n0 + ty * TN + j);
                    v.x += bv.x; v.y += bv.y; v.z += bv.z; v.w += bv.w;
                }
                *reinterpret_cast<float4*>(C + (size_t)r * N + n0 + ty * TN + j) = v;
            }
        }
    }
}

// ---------------- SpMM over sorted CSR: dst[i] = sum val * src[col] (+bias)(relu)
template<int F, bool RELU>
__global__ void spmm_kernel(const float* __restrict__ src, const float* __restrict__ bias,
                            float* __restrict__ dst, int nrows) {
    constexpr int TPR = F / 4;         // threads per row (float4 per thread)
    constexpr int RPB = 256 / TPR;     // rows per block
    const int lane = threadIdx.x % TPR;
    const int row  = blockIdx.x * RPB + threadIdx.x / TPR;
    if (row >= nrows) return;

    const int s = g_rowptr[row];
    const int e = g_rowptr[row + 1];
    float4 acc = make_float4(0.f, 0.f, 0.f, 0.f);
    for (int j = s; j < e; j++) {
        int   c = g_colsorted[j];
        float v = g_valsorted[j];
        float4 xv = *reinterpret_cast<const float4*>(src + (size_t)c * F + lane * 4);
        acc.x += v * xv.x; acc.y += v * xv.y;
        acc.z += v * xv.z; acc.w += v * xv.w;
    }
    float4 b = *reinterpret_cast<const float4*>(bias + lane * 4);
    acc.x += b.x; acc.y += b.y; acc.z += b.z; acc.w += b.w;
    if (RELU) {
        acc.x = fmaxf(acc.x, 0.f); acc.y = fmaxf(acc.y, 0.f);
        acc.z = fmaxf(acc.z, 0.f); acc.w = fmaxf(acc.w, 0.f);
    }
    *reinterpret_cast<float4*>(dst + (size_t)row * F + lane * 4) = acc;
}

// ---------------- log_softmax over 64 classes (warp per row, 2 vals/lane) --------
__global__ void k_logsoftmax(const float* __restrict__ z, float* __restrict__ out, int nrows) {
    int row  = blockIdx.x * 8 + threadIdx.x / 32;
    int lane = threadIdx.x & 31;
    if (row >= nrows) return;
    float2 v = *reinterpret_cast<const float2*>(z + (size_t)row * F_CLS + lane * 2);
    float m = fmaxf(v.x, v.y);
    #pragma unroll
    for (int off = 16; off; off >>= 1) m = fmaxf(m, __shfl_xor_sync(0xffffffffu, m, off));
    float s = expf(v.x - m) + expf(v.y - m);
    #pragma unroll
    for (int off = 16; off; off >>= 1) s += __shfl_xor_sync(0xffffffffu, s, off);
    float ls = m + logf(s);
    float2 o; o.x = v.x - ls; o.y = v.y - ls;
    *reinterpret_cast<float2*>(out + (size_t)row * F_CLS + lane * 2) = o;
}

// ---------------- launch ---------------------------------------------------------
extern "C" void kernel_launch(void* const* d_in, const int* in_sizes, int n_in,
                              void* d_out, int out_size) {
    const float* x    = (const float*)d_in[0];
    const float* vals = (const float*)d_in[1];
    const float* W1   = (const float*)d_in[2];
    const float* b1   = (const float*)d_in[3];
    const float* W2   = (const float*)d_in[4];
    const float* b2   = (const float*)d_in[5];
    const float* W3   = (const float*)d_in[6];
    const float* b3   = (const float*)d_in[7];
    const int*   rows = (const int*)d_in[8];
    const int*   cols = (const int*)d_in[9];

    const int E = in_sizes[8];
    const int M = in_sizes[0] / F_IN;   // 100000

    float* out1 = (float*)d_out;                      // log_softmax [M, 64]
    float* out2 = (float*)d_out + (size_t)M * F_CLS;  // projection  [M, 128]

    float *pXW1, *ph, *pHW2, *pz;
    cudaGetSymbolAddress((void**)&pXW1, g_XW1);
    cudaGetSymbolAddress((void**)&ph,   g_h);
    cudaGetSymbolAddress((void**)&pHW2, g_HW2);
    cudaGetSymbolAddress((void**)&pz,   g_z);

    // 1) bucket edges into CSR (reused by both spmms)
    k_zero_counts<<<(M + 255) / 256, 256>>>(M);
    k_hist<<<(E + 255) / 256, 256>>>(rows, E);
    k_scan<<<1, 1024>>>(M);
    k_scatter<<<(E + 255) / 256, 256>>>(rows, cols, vals, E);

    // 2) XW1 = x @ W1
    {
        dim3 g(F_HID / 128, (M + 127) / 128);
        sgemm<128, 128, 8, 8, 8, false, false><<<g, 256>>>(x, W1, nullptr, pXW1, M, F_HID, F_IN);
    }
    // 3) h = relu(spmm(adj, XW1) + b1)
    spmm_kernel<F_HID, true><<<(M + 3) / 4, 256>>>(pXW1, b1, ph, M);

    // 4) HW2 = h @ W2
    {
        dim3 g(F_CLS / 64, (M + 127) / 128);
        sgemm<128, 64, 8, 8, 8, false, false><<<g, 128>>>(ph, W2, nullptr, pHW2, M, F_CLS, F_HID);
    }
    // 5) z = spmm(adj, HW2) + b2
    spmm_kernel<F_CLS, false><<<(M + 15) / 16, 256>>>(pHW2, b2, pz, M);

    // 6) out1 = log_softmax(z)
    k_logsoftmax<<<(M + 7) / 8, 256>>>(pz, out1, M);

    // 7) out2 = relu(z) @ W3 + b3
    {
        dim3 g(F_PROJ / 128, (M + 127) / 128);
        sgemm<128, 128, 8, 8, 8, true, true><<<g, 256>>>(pz, W3, b3, out2, M, F_PROJ, F_CLS);
    }
}

// round 3
// speedup vs baseline: 1.5437x; 1.5437x over previous
#include <cuda_runtime.h>
#include <cuda_bf16.h>
#include <cstdint>

#define NN 100000
#define NN_PAD 100096      // 782 * 128
#define NE_MAX 3400000
#define F_IN   512
#define F_HID  256
#define F_CLS  64
#define F_PROJ 128

// ---------------- scratch (static device globals; no allocation) ----------------
__device__ float g_XW1[(size_t)NN * F_HID];   // x @ W1 (fp32)
__device__ float g_HW2[(size_t)NN * F_CLS];   // h @ W2 (fp32)
__device__ float g_z  [(size_t)NN * F_CLS];   // spmm + b2
__device__ __nv_bfloat16 g_xhi[(size_t)NN_PAD * F_IN];
__device__ __nv_bfloat16 g_xlo[(size_t)NN_PAD * F_IN];
__device__ __nv_bfloat16 g_hhi[(size_t)NN_PAD * F_HID];
__device__ __nv_bfloat16 g_hlo[(size_t)NN_PAD * F_HID];
__device__ __nv_bfloat16 g_w1thi[F_HID * F_IN];   // W1^T [256,512]
__device__ __nv_bfloat16 g_w1tlo[F_HID * F_IN];
__device__ __nv_bfloat16 g_w2thi[F_CLS * F_HID];  // W2^T [64,256]
__device__ __nv_bfloat16 g_w2tlo[F_CLS * F_HID];
__device__ int   g_counts[NN];
__device__ int   g_rowptr[NN + 1];
__device__ int   g_cursor[NN];
__device__ int   g_colsorted[NE_MAX];
__device__ float g_valsorted[NE_MAX];

// ---------------- PTX helpers (baseline sm_90-safe; NO tcgen05) -------------------
__device__ __forceinline__ uint32_t smem_to_u32(const void* p) {
    uint32_t a;
    asm("{ .reg .u64 t; cvta.to.shared.u64 t, %1; cvt.u32.u64 %0, t; }" : "=r"(a) : "l"(p));
    return a;
}
#define CP_ASYNC16(dst, src) \
    asm volatile("cp.async.cg.shared.global [%0], [%1], 16;" :: "r"(dst), "l"(src))
#define CP_COMMIT() asm volatile("cp.async.commit_group;" ::: "memory")
#define CP_WAIT(N)  asm volatile("cp.async.wait_group %0;" :: "n"(N) : "memory")

#define LDSM_X4(r, addr) \
    asm volatile("ldmatrix.sync.aligned.m8n8.x4.shared.b16 {%0,%1,%2,%3}, [%4];" \
        : "=r"((r)[0]), "=r"((r)[1]), "=r"((r)[2]), "=r"((r)[3]) : "r"(addr))

__device__ __forceinline__ void mma16816(float* c, const uint32_t* a, uint32_t b0, uint32_t b1) {
    asm volatile("mma.sync.aligned.m16n8k16.row.col.f32.bf16.bf16.f32 "
        "{%0,%1,%2,%3}, {%4,%5,%6,%7}, {%8,%9}, {%0,%1,%2,%3};"
        : "+f"(c[0]), "+f"(c[1]), "+f"(c[2]), "+f"(c[3])
        : "r"(a[0]), "r"(a[1]), "r"(a[2]), "r"(a[3]), "r"(b0), "r"(b1));
}

// XOR swizzle for 64B-row tiles: row r, 16B-column c16 (0..3)
__device__ __forceinline__ uint32_t swz(int r, int c16) {
    return (uint32_t)(r * 64 + ((c16 ^ ((r >> 1) & 3)) << 4));
}

// ---------------- edge bucketing --------------------------------------------------
__global__ void k_zero_counts(int n) {
    int i = blockIdx.x * blockDim.x + threadIdx.x;
    if (i < n) g_counts[i] = 0;
}
__global__ void k_hist(const int* __restrict__ rows, int E) {
    int e = blockIdx.x * blockDim.x + threadIdx.x;
    if (e < E) atomicAdd(&g_counts[rows[e]], 1);
}
__global__ void k_scan(int n) {
    __shared__ int part[1024];
    int tid = threadIdx.x;
    int per = (n + 1023) >> 10;
    int st = tid * per;
    int en = st + per; if (en > n) en = n;
    int s = 0;
    for (int i = st; i < en; i++) s += g_counts[i];
    part[tid] = s;
    __syncthreads();
    #pragma unroll
    for (int off = 1; off < 1024; off <<= 1) {
        int v = (tid >= off) ? part[tid - off] : 0;
        __syncthreads();
        part[tid] += v;
        __syncthreads();
    }
    int base = (tid == 0) ? 0 : part[tid - 1];
    for (int i = st; i < en; i++) {
        int c = g_counts[i];
        g_rowptr[i] = base;
        g_cursor[i] = base;
        base += c;
    }
    if (tid == 1023) g_rowptr[n] = part[1023];
}
__global__ void k_scatter(const int* __restrict__ rows, const int* __restrict__ cols,
                          const float* __restrict__ vals, int E) {
    int e = blockIdx.x * blockDim.x + threadIdx.x;
    if (e < E) {
        int r = rows[e];
        int p = atomicAdd(&g_cursor[r], 1);
        g_colsorted[p] = cols[e];
        g_valsorted[p] = vals[e];
    }
}

// ---------------- fp32 -> bf16 hi/lo split (with row padding) --------------------
__global__ void k_split_pad(const float* __restrict__ in, __nv_bfloat16* __restrict__ hi,
                            __nv_bfloat16* __restrict__ lo, int rows, int cols, int rows_pad) {
    size_t i4 = (size_t)blockIdx.x * blockDim.x + threadIdx.x;
    size_t total4 = (size_t)rows_pad * cols / 4;
    if (i4 >= total4) return;
    size_t i = i4 * 4;
    int r = (int)(i / cols);
    float4 v = (r < rows) ? *reinterpret_cast<const float4*>(in + i)
                          : make_float4(0.f, 0.f, 0.f, 0.f);
    __nv_bfloat16 hx = __float2bfloat16(v.x), hy = __float2bfloat16(v.y),
                  hz = __float2bfloat16(v.z), hw = __float2bfloat16(v.w);
    __nv_bfloat16 lx = __float2bfloat16(v.x - __bfloat162float(hx));
    __nv_bfloat16 ly = __float2bfloat16(v.y - __bfloat162float(hy));
    __nv_bfloat16 lz = __float2bfloat16(v.z - __bfloat162float(hz));
    __nv_bfloat16 lw = __float2bfloat16(v.w - __bfloat162float(hw));
    __nv_bfloat162 h0; h0.x = hx; h0.y = hy;
    __nv_bfloat162 h1; h1.x = hz; h1.y = hw;
    __nv_bfloat162 l0; l0.x = lx; l0.y = ly;
    __nv_bfloat162 l1; l1.x = lz; l1.y = lw;
    uint2 hp, lp;
    hp.x = *(uint32_t*)&h0; hp.y = *(uint32_t*)&h1;
    lp.x = *(uint32_t*)&l0; lp.y = *(uint32_t*)&l1;
    *reinterpret_cast<uint2*>(hi + i) = hp;
    *reinterpret_cast<uint2*>(lo + i) = lp;
}

// ---------------- transpose + split: W[K,N] -> T[N,K] bf16 hi/lo ------------------
__global__ void k_transpose_split(const float* __restrict__ W, __nv_bfloat16* __restrict__ Thi,
                                  __nv_bfloat16* __restrict__ Tlo, int K, int N) {
    int i = blockIdx.x * blockDim.x + threadIdx.x;
    if (i >= K * N) return;
    int k = i / N, n = i % N;
    float v = W[i];
    __nv_bfloat16 h = __float2bfloat16(v);
    __nv_bfloat16 l = __float2bfloat16(v - __bfloat162float(h));
    Thi[(size_t)n * K + k] = h;
    Tlo[(size_t)n * K + k] = l;
}

// ---------------- split-bf16 tensor-core GEMM via mma.sync -------------------------
// C[M, N_TOT] tile (128 x BN) = A[M,K] @ Bt[N,K]^T, A/B given as hi/lo bf16.
// 8 warps: 4 (m) x 2 (n); warp tile 32 x BN/2. BK=32, 3-stage cp.async pipeline.
template<int BN, int K_TOT, int N_TOT>
__global__ void __launch_bounds__(256, 1) gemm_mma(
    const __nv_bfloat16* __restrict__ Ahi, const __nv_bfloat16* __restrict__ Alo,
    const __nv_bfloat16* __restrict__ Bhi, const __nv_bfloat16* __restrict__ Blo,
    float* __restrict__ C, int Mrows)
{
    constexpr int NC = K_TOT / 32;          // k-chunks
    constexpr int SS = 16384 + BN * 128;    // stage bytes: Ahi+Alo (16K) + Bhi+Blo
    constexpr int NT16 = BN / 32;           // n16 ldmatrix groups per warp
    constexpr int NT8  = BN / 16;           // n8 mma tiles per warp

    extern __shared__ __align__(128) char smem[];
    const uint32_t sb = smem_to_u32(smem);
    const int tid = threadIdx.x;
    const int wid = tid >> 5, lane = tid & 31;
    const int warpM = wid & 3, warpN = wid >> 2;
    const int m0 = blockIdx.x * 128;
    const int n_off = blockIdx.y * BN;
    const int wm0 = warpM * 32;
    const int wn0 = warpN * (BN / 2);

    float acc[2][NT8][4];
    #pragma unroll
    for (int i = 0; i < 2; i++)
        #pragma unroll
        for (int j = 0; j < NT8; j++)
            #pragma unroll
            for (int q = 0; q < 4; q++) acc[i][j][q] = 0.f;

    auto load_chunk = [&](int kc) {
        const uint32_t sd = sb + (uint32_t)(kc % 3) * SS;
        // A hi+lo: 1024 x 16B
        #pragma unroll
        for (int i = tid; i < 1024; i += 256) {
            int buf = i >> 9, idx = i & 511;
            int r = idx >> 2, c16 = idx & 3;
            uint32_t dst = sd + (uint32_t)buf * 8192 + swz(r, c16);
            const char* g = (const char*)((buf ? Alo : Ahi) + (size_t)(m0 + r) * K_TOT)
                            + kc * 64 + c16 * 16;
            CP_ASYNC16(dst, g);
        }
        // B hi+lo: 2*BN*4 x 16B
        #pragma unroll
        for (int i = tid; i < 2 * BN * 4; i += 256) {
            int buf = (i >= BN * 4);
            int idx = buf ? i - BN * 4 : i;
            int r = idx >> 2, c16 = idx & 3;
            uint32_t dst = sd + 16384 + (uint32_t)buf * (BN * 64) + swz(r, c16);
            const char* g = (const char*)((buf ? Blo : Bhi) + (size_t)(n_off + r) * K_TOT)
                            + kc * 64 + c16 * 16;
            CP_ASYNC16(dst, g);
        }
        CP_COMMIT();
    };

    load_chunk(0);
    load_chunk(1);

    for (int kc = 0; kc < NC; kc++) {
        CP_WAIT(1);
        __syncthreads();
        if (kc + 2 < NC) load_chunk(kc + 2);

        const uint32_t sA_hi = sb + (uint32_t)(kc % 3) * SS;
        const uint32_t sA_lo = sA_hi + 8192;
        const uint32_t sB_hi = sA_lo + 8192;
        const uint32_t sB_lo = sB_hi + BN * 64;

        #pragma unroll
        for (int ks = 0; ks < 2; ks++) {
            uint32_t ahi[2][4], alo[2][4];
            #pragma unroll
            for (int mt = 0; mt < 2; mt++) {
                int row = wm0 + mt * 16 + (lane & 15);
                int c16 = ks * 2 + (lane >> 4);
                LDSM_X4(ahi[mt], sA_hi + swz(row, c16));
                LDSM_X4(alo[mt], sA_lo + swz(row, c16));
            }
            uint32_t bhi[NT16][4], blo[NT16][4];
            #pragma unroll
            for (int g = 0; g < NT16; g++) {
                int row = wn0 + g * 16 + (lane & 15);
                int c16 = ks * 2 + (lane >> 4);
                LDSM_X4(bhi[g], sB_hi + swz(row, c16));
                LDSM_X4(blo[g], sB_lo + swz(row, c16));
            }
            #pragma unroll
            for (int mt = 0; mt < 2; mt++)
                #pragma unroll
                for (int g = 0; g < NT16; g++)
                    #pragma unroll
                    for (int h = 0; h < 2; h++) {
                        int nt = g * 2 + h;
                        mma16816(acc[mt][nt], ahi[mt], bhi[g][h], bhi[g][2 + h]);
                        mma16816(acc[mt][nt], alo[mt], bhi[g][h], bhi[g][2 + h]);
                        mma16816(acc[mt][nt], ahi[mt], blo[g][h], blo[g][2 + h]);
                    }
        }
        __syncthreads();
    }

    // epilogue: fragment -> C (fp32)
    #pragma unroll
    for (int mt = 0; mt < 2; mt++) {
        int m = m0 + wm0 + mt * 16 + (lane >> 2);
        #pragma unroll
        for (int nt = 0; nt < NT8; nt++) {
            int n = n_off + wn0 + nt * 8 + (lane & 3) * 2;
            if (m < Mrows) {
                float2 v0; v0.x = acc[mt][nt][0]; v0.y = acc[mt][nt][1];
                *reinterpret_cast<float2*>(C + (size_t)m * N_TOT + n) = v0;
            }
            if (m + 8 < Mrows) {
                float2 v1; v1.x = acc[mt][nt][2]; v1.y = acc[mt][nt][3];
                *reinterpret_cast<float2*>(C + (size_t)(m + 8) * N_TOT + n) = v1;
            }
        }
    }
}

// ---------------- SGEMM (fp32, used for GEMM3 only) -------------------------------
template<int BM, int BN, int BK, int TM, int TN, bool RELU_A, bool ADD_BIAS>
__global__ void sgemm(const float* __restrict__ A, const float* __restrict__ B,
                      const float* __restrict__ bias, float* __restrict__ C,
                      int M, int N, int K) {
    constexpr int NT = (BM / TM) * (BN / TN);
    __shared__ float As[BK][BM];
    __shared__ float Bs[BK][BN];

    const int tid = threadIdx.x;
    const int tx = tid / (BN / TN);
    const int ty = tid % (BN / TN);
    const int m0 = blockIdx.y * BM;
    const int n0 = blockIdx.x * BN;

    float acc[TM][TN];
    #pragma unroll
    for (int i = 0; i < TM; i++)
        #pragma unroll
        for (int j = 0; j < TN; j++) acc[i][j] = 0.f;

    for (int k0 = 0; k0 < K; k0 += BK) {
        #pragma unroll
        for (int i = tid; i < BM * BK / 4; i += NT) {
            int r  = i / (BK / 4);
            int ks = i % (BK / 4);
            float4 v;
            if (m0 + r < M)
                v = *reinterpret_cast<const float4*>(A + (size_t)(m0 + r) * K + k0 + ks * 4);
            else
                v = make_float4(0.f, 0.f, 0.f, 0.f);
            if (RELU_A) {
                v.x = fmaxf(v.x, 0.f); v.y = fmaxf(v.y, 0.f);
                v.z = fmaxf(v.z, 0.f); v.w = fmaxf(v.w, 0.f);
            }
            As[ks * 4 + 0][r] = v.x;
            As[ks * 4 + 1][r] = v.y;
            As[ks * 4 + 2][r] = v.z;
            As[ks * 4 + 3][r] = v.w;
        }
        #pragma unroll
        for (int i = tid; i < BK * BN / 4; i += NT) {
            int r  = i / (BN / 4);
            int cs = i % (BN / 4);
            *reinterpret_cast<float4*>(&Bs[r][cs * 4]) =
                *reinterpret_cast<const float4*>(B + (size_t)(k0 + r) * N + n0 + cs * 4);
        }
        __syncthreads();

        #pragma unroll
        for (int k = 0; k < BK; k++) {
            float a[TM], b[TN];
            #pragma unroll
            for (int i = 0; i < TM; i += 4) {
                float4 v = *reinterpret_cast<const float4*>(&As[k][tx * TM + i]);
                a[i] = v.x; a[i + 1] = v.y; a[i + 2] = v.z; a[i + 3] = v.w;
            }
            #pragma unroll
            for (int j = 0; j < TN; j += 4) {
                float4 v = *reinterpret_cast<const float4*>(&Bs[k][ty * TN + j]);
                b[j] = v.x; b[j + 1] = v.y; b[j + 2] = v.z; b[j + 3] = v.w;
            }
            #pragma unroll
            for (int i = 0; i < TM; i++)
                #pragma unroll
                for (int j = 0; j < TN; j++)
                    acc[i][j] += a[i] * b[j];
        }
        __syncthreads();
    }

    #pragma unroll
    for (int i = 0; i < TM; i++) {
        int r = m0 + tx * TM + i;
        if (r < M) {
            #pragma unroll
            for (int j = 0; j < TN; j += 4) {
                float4 v;
                v.x = acc[i][j];     v.y = acc[i][j + 1];
                v.z = acc[i][j + 2]; v.w = acc[i][j + 3];
                if (ADD_BIAS) {
                    float4 bv = *reinterpret_cast<const float4*>(bias + n0 + ty * TN + j);
                    v.x += bv.x; v.y += bv.y; v.z += bv.z; v.w += bv.w;
                }
                *reinterpret_cast<float4*>(C + (size_t)r * N + n0 + ty * TN + j) = v;
            }
        }
    }
}

// ---------------- SpMM over sorted CSR --------------------------------------------
template<int F, bool RELU>
__global__ void spmm_kernel(const float* __restrict__ src, const float* __restrict__ bias,
                            float* __restrict__ dst, int nrows) {
    constexpr int TPR = F / 4;
    constexpr int RPB = 256 / TPR;
    const int lane = threadIdx.x % TPR;
    const int row  = blockIdx.x * RPB + threadIdx.x / TPR;
    if (row >= nrows) return;

    const int s = g_rowptr[row];
    const int e = g_rowptr[row + 1];
    float4 acc = make_float4(0.f, 0.f, 0.f, 0.f);
    for (int j = s; j < e; j++) {
        int   c = g_colsorted[j];
        float v = g_valsorted[j];
        float4 xv = *reinterpret_cast<const float4*>(src + (size_t)c * F + lane * 4);
        acc.x += v * xv.x; acc.y += v * xv.y;
        acc.z += v * xv.z; acc.w += v * xv.w;
    }
    float4 b = *reinterpret_cast<const float4*>(bias + lane * 4);
    acc.x += b.x; acc.y += b.y; acc.z += b.z; acc.w += b.w;
    if (RELU) {
        acc.x = fmaxf(acc.x, 0.f); acc.y = fmaxf(acc.y, 0.f);
        acc.z = fmaxf(acc.z, 0.f); acc.w = fmaxf(acc.w, 0.f);
    }
    *reinterpret_cast<float4*>(dst + (size_t)row * F + lane * 4) = acc;
}

// split-bf16-out variant (spmm1: h = relu(spmm + b1) -> hi/lo bf16)
template<int F>
__global__ void spmm_split_kernel(const float* __restrict__ src, const float* __restrict__ bias,
                                  __nv_bfloat16* __restrict__ hi, __nv_bfloat16* __restrict__ lo,
                                  int nrows) {
    constexpr int TPR = F / 4;
    constexpr int RPB = 256 / TPR;
    const int lane = threadIdx.x % TPR;
    const int row  = blockIdx.x * RPB + threadIdx.x / TPR;
    if (row >= nrows) return;

    const int s = g_rowptr[row];
    const int e = g_rowptr[row + 1];
    float4 acc = make_float4(0.f, 0.f, 0.f, 0.f);
    for (int j = s; j < e; j++) {
        int   c = g_colsorted[j];
        float v = g_valsorted[j];
        float4 xv = *reinterpret_cast<const float4*>(src + (size_t)c * F + lane * 4);
        acc.x += v * xv.x; acc.y += v * xv.y;
        acc.z += v * xv.z; acc.w += v * xv.w;
    }
    float4 b = *reinterpret_cast<const float4*>(bias + lane * 4);
    acc.x = fmaxf(acc.x + b.x, 0.f); acc.y = fmaxf(acc.y + b.y, 0.f);
    acc.z = fmaxf(acc.z + b.z, 0.f); acc.w = fmaxf(acc.w + b.w, 0.f);

    __nv_bfloat16 hx = __float2bfloat16(acc.x), hy = __float2bfloat16(acc.y),
                  hz = __float2bfloat16(acc.z), hw = __float2bfloat16(acc.w);
    __nv_bfloat16 lx = __float2bfloat16(acc.x - __bfloat162float(hx));
    __nv_bfloat16 ly = __float2bfloat16(acc.y - __bfloat162float(hy));
    __nv_bfloat16 lz = __float2bfloat16(acc.z - __bfloat162float(hz));
    __nv_bfloat16 lw = __float2bfloat16(acc.w - __bfloat162float(hw));
    __nv_bfloat162 h0; h0.x = hx; h0.y = hy;
    __nv_bfloat162 h1; h1.x = hz; h1.y = hw;
    __nv_bfloat162 l0; l0.x = lx; l0.y = ly;
    __nv_bfloat162 l1; l1.x = lz; l1.y = lw;
    uint2 hp, lp;
    hp.x = *(uint32_t*)&h0; hp.y = *(uint32_t*)&h1;
    lp.x = *(uint32_t*)&l0; lp.y = *(uint32_t*)&l1;
    size_t off = (size_t)row * F + lane * 4;
    *reinterpret_cast<uint2*>(hi + off) = hp;
    *reinterpret_cast<uint2*>(lo + off) = lp;
}

// ---------------- log_softmax over 64 classes --------------------------------------
__global__ void k_logsoftmax(const float* __restrict__ z, float* __restrict__ out, int nrows) {
    int row  = blockIdx.x * 8 + threadIdx.x / 32;
    int lane = threadIdx.x & 31;
    if (row >= nrows) return;
    float2 v = *reinterpret_cast<const float2*>(z + (size_t)row * F_CLS + lane * 2);
    float m = fmaxf(v.x, v.y);
    #pragma unroll
    for (int off = 16; off; off >>= 1) m = fmaxf(m, __shfl_xor_sync(0xffffffffu, m, off));
    float s = expf(v.x - m) + expf(v.y - m);
    #pragma unroll
    for (int off = 16; off; off >>= 1) s += __shfl_xor_sync(0xffffffffu, s, off);
    float ls = m + logf(s);
    float2 o; o.x = v.x - ls; o.y = v.y - ls;
    *reinterpret_cast<float2*>(out + (size_t)row * F_CLS + lane * 2) = o;
}

// ---------------- launch ------------------------------------------------------------
extern "C" void kernel_launch(void* const* d_in, const int* in_sizes, int n_in,
                              void* d_out, int out_size) {
    const float* x    = (const float*)d_in[0];
    const float* vals = (const float*)d_in[1];
    const float* W1   = (const float*)d_in[2];
    const float* b1   = (const float*)d_in[3];
    const float* W2   = (const float*)d_in[4];
    const float* b2   = (const float*)d_in[5];
    const float* W3   = (const float*)d_in[6];
    const float* b3   = (const float*)d_in[7];
    const int*   rows = (const int*)d_in[8];
    const int*   cols = (const int*)d_in[9];

    const int E = in_sizes[8];
    const int M = in_sizes[0] / F_IN;   // 100000

    float* out1 = (float*)d_out;                      // log_softmax [M, 64]
    float* out2 = (float*)d_out + (size_t)M * F_CLS;  // projection  [M, 128]

    float *pXW1, *pHW2, *pz;
    __nv_bfloat16 *pxhi, *pxlo, *phhi, *phlo, *pw1thi, *pw1tlo, *pw2thi, *pw2tlo;
    cudaGetSymbolAddress((void**)&pXW1, g_XW1);
    cudaGetSymbolAddress((void**)&pHW2, g_HW2);
    cudaGetSymbolAddress((void**)&pz,   g_z);
    cudaGetSymbolAddress((void**)&pxhi, g_xhi);
    cudaGetSymbolAddress((void**)&pxlo, g_xlo);
    cudaGetSymbolAddress((void**)&phhi, g_hhi);
    cudaGetSymbolAddress((void**)&phlo, g_hlo);
    cudaGetSymbolAddress((void**)&pw1thi, g_w1thi);
    cudaGetSymbolAddress((void**)&pw1tlo, g_w1tlo);
    cudaGetSymbolAddress((void**)&pw2thi, g_w2thi);
    cudaGetSymbolAddress((void**)&pw2tlo, g_w2tlo);

    // dynamic smem: 3 stages
    constexpr int SMEM1 = 3 * (16384 + 128 * 128);  // 98304
    constexpr int SMEM2 = 3 * (16384 + 64 * 128);   // 73728
    cudaFuncSetAttribute(gemm_mma<128, F_IN, F_HID>,
                         cudaFuncAttributeMaxDynamicSharedMemorySize, SMEM1);
    cudaFuncSetAttribute(gemm_mma<64, F_HID, F_CLS>,
                         cudaFuncAttributeMaxDynamicSharedMemorySize, SMEM2);

    const int MT = NN_PAD / 128;  // 782 row tiles

    // 1) bucket edges into CSR (reused by both spmms)
    k_zero_counts<<<(M + 255) / 256, 256>>>(M);
    k_hist<<<(E + 255) / 256, 256>>>(rows, E);
    k_scan<<<1, 1024>>>(M);
    k_scatter<<<(E + 255) / 256, 256>>>(rows, cols, vals, E);

    // 2) split conversions
    {
        size_t total4 = (size_t)NN_PAD * F_IN / 4;
        k_split_pad<<<(unsigned)((total4 + 255) / 256), 256>>>(x, pxhi, pxlo, M, F_IN, NN_PAD);
    }
    k_transpose_split<<<(F_IN * F_HID + 255) / 256, 256>>>(W1, pw1thi, pw1tlo, F_IN, F_HID);
    k_transpose_split<<<(F_HID * F_CLS + 255) / 256, 256>>>(W2, pw2thi, pw2tlo, F_HID, F_CLS);

    // 3) XW1 = x @ W1  (tensor cores, split-bf16)
    {
        dim3 g(MT, F_HID / 128);
        gemm_mma<128, F_IN, F_HID><<<g, 256, SMEM1>>>(pxhi, pxlo, pw1thi, pw1tlo, pXW1, M);
    }

    // 4) h = relu(spmm(adj, XW1) + b1) -> bf16 hi/lo
    spmm_split_kernel<F_HID><<<(M + 3) / 4, 256>>>(pXW1, b1, phhi, phlo, M);

    // 5) HW2 = h @ W2 (tensor cores, split-bf16)
    {
        dim3 g(MT, 1);
        gemm_mma<64, F_HID, F_CLS><<<g, 256, SMEM2>>>(phhi, phlo, pw2thi, pw2tlo, pHW2, M);
    }

    // 6) z = spmm(adj, HW2) + b2
    spmm_kernel<F_CLS, false><<<(M + 15) / 16, 256>>>(pHW2, b2, pz, M);

    // 7) out1 = log_softmax(z)
    k_logsoftmax<<<(M + 7) / 8, 256>>>(pz, out1, M);

    // 8) out2 = relu(z) @ W3 + b3 (fp32 SGEMM; K=64 too small for TC to pay off)
    {
        dim3 g(F_PROJ / 128, (M + 127) / 128);
        sgemm<128, 128, 8, 8, 8, true, true><<<g, 256>>>(pz, W3, b3, out2, M, F_PROJ, F_CLS);
    }
}

// round 5
// speedup vs baseline: 1.8637x; 1.2073x over previous
#include <cuda_runtime.h>
#include <cuda_bf16.h>
#include <cuda_fp16.h>
#include <cstdint>

#define NN 100000
#define NN_PAD 100096      // 782 * 128
#define NE_MAX 3400000
#define F_IN   512
#define F_HID  256
#define F_CLS  64
#define F_PROJ 128

// ---------------- scratch (static device globals; no allocation) ----------------
__device__ __half g_XW1h[(size_t)NN * F_HID];   // x @ W1 (fp16)
__device__ __half g_HW2h[(size_t)NN * F_CLS];   // h @ W2 (fp16)
__device__ float  g_z   [(size_t)NN * F_CLS];   // spmm + b2 (fp32)
__device__ __nv_bfloat16 g_xhi[(size_t)NN_PAD * F_IN];
__device__ __nv_bfloat16 g_xlo[(size_t)NN_PAD * F_IN];
__device__ __nv_bfloat16 g_hhi[(size_t)NN_PAD * F_HID];
__device__ __nv_bfloat16 g_hlo[(size_t)NN_PAD * F_HID];
__device__ __nv_bfloat16 g_zhi[(size_t)NN_PAD * F_CLS];   // relu(z) split
__device__ __nv_bfloat16 g_zlo[(size_t)NN_PAD * F_CLS];
__device__ __nv_bfloat16 g_w1thi[F_HID * F_IN];   // W1^T [256,512]
__device__ __nv_bfloat16 g_w1tlo[F_HID * F_IN];
__device__ __nv_bfloat16 g_w2thi[F_CLS * F_HID];  // W2^T [64,256]
__device__ __nv_bfloat16 g_w2tlo[F_CLS * F_HID];
__device__ __nv_bfloat16 g_w3thi[F_PROJ * F_CLS]; // W3^T [128,64]
__device__ __nv_bfloat16 g_w3tlo[F_PROJ * F_CLS];
__device__ int   g_counts[NN];
__device__ int   g_rowptr[NN + 1];
__device__ int   g_cursor[NN];
__device__ int   g_colsorted[NE_MAX];
__device__ float g_valsorted[NE_MAX];

// ---------------- PTX helpers (sm_103-safe; no tcgen05) ---------------------------
__device__ __forceinline__ uint32_t smem_to_u32(const void* p) {
    uint32_t a;
    asm("{ .reg .u64 t; cvta.to.shared.u64 t, %1; cvt.u32.u64 %0, t; }" : "=r"(a) : "l"(p));
    return a;
}
#define CP_ASYNC16(dst, src) \
    asm volatile("cp.async.cg.shared.global [%0], [%1], 16;" :: "r"(dst), "l"(src))
#define CP_COMMIT() asm volatile("cp.async.commit_group;" ::: "memory")
#define CP_WAIT(N)  asm volatile("cp.async.wait_group %0;" :: "n"(N) : "memory")

#define LDSM_X4(r, addr) \
    asm volatile("ldmatrix.sync.aligned.m8n8.x4.shared.b16 {%0,%1,%2,%3}, [%4];" \
        : "=r"((r)[0]), "=r"((r)[1]), "=r"((r)[2]), "=r"((r)[3]) : "r"(addr))

__device__ __forceinline__ void mma16816(float* c, const uint32_t* a, uint32_t b0, uint32_t b1) {
    asm volatile("mma.sync.aligned.m16n8k16.row.col.f32.bf16.bf16.f32 "
        "{%0,%1,%2,%3}, {%4,%5,%6,%7}, {%8,%9}, {%0,%1,%2,%3};"
        : "+f"(c[0]), "+f"(c[1]), "+f"(c[2]), "+f"(c[3])
        : "r"(a[0]), "r"(a[1]), "r"(a[2]), "r"(a[3]), "r"(b0), "r"(b1));
}

// XOR swizzle for 64B-row tiles: row r, 16B-column c16 (0..3)
__device__ __forceinline__ uint32_t swz(int r, int c16) {
    return (uint32_t)(r * 64 + ((c16 ^ ((r >> 1) & 3)) << 4));
}

// pack 2 floats -> hi bf16x2 + lo bf16x2 (residual)
__device__ __forceinline__ void split2(float a, float b, uint32_t& hi, uint32_t& lo) {
    __nv_bfloat16 ha = __float2bfloat16(a), hb = __float2bfloat16(b);
    __nv_bfloat16 la = __float2bfloat16(a - __bfloat162float(ha));
    __nv_bfloat16 lb = __float2bfloat16(b - __bfloat162float(hb));
    __nv_bfloat162 h; h.x = ha; h.y = hb;
    __nv_bfloat162 l; l.x = la; l.y = lb;
    hi = *(uint32_t*)&h;
    lo = *(uint32_t*)&l;
}

// epilogue store helpers (fp32 or fp16 output)
__device__ __forceinline__ void store2(float* p, float x, float y) {
    *reinterpret_cast<float2*>(p) = make_float2(x, y);
}
__device__ __forceinline__ void store2(__half* p, float x, float y) {
    *reinterpret_cast<__half2*>(p) = __floats2half2_rn(x, y);
}

// ---------------- edge bucketing --------------------------------------------------
__global__ void k_zero_counts(int n) {
    int i = blockIdx.x * blockDim.x + threadIdx.x;
    if (i < n) g_counts[i] = 0;
}
__global__ void k_hist(const int* __restrict__ rows, int E) {
    int base = (blockIdx.x * blockDim.x + threadIdx.x) * 4;
    #pragma unroll
    for (int q = 0; q < 4; q++) {
        int e = base + q;
        if (e < E) atomicAdd(&g_counts[rows[e]], 1);
    }
}
__global__ void k_scan(int n) {
    __shared__ int part[1024];
    int tid = threadIdx.x;
    int per = (n + 1023) >> 10;
    int st = tid * per;
    int en = st + per; if (en > n) en = n;
    int s = 0;
    for (int i = st; i < en; i++) s += g_counts[i];
    part[tid] = s;
    __syncthreads();
    #pragma unroll
    for (int off = 1; off < 1024; off <<= 1) {
        int v = (tid >= off) ? part[tid - off] : 0;
        __syncthreads();
        part[tid] += v;
        __syncthreads();
    }
    int base = (tid == 0) ? 0 : part[tid - 1];
    for (int i = st; i < en; i++) {
        int c = g_counts[i];
        g_rowptr[i] = base;
        g_cursor[i] = base;
        base += c;
    }
    if (tid == 1023) g_rowptr[n] = part[1023];
}
__global__ void k_scatter(const int* __restrict__ rows, const int* __restrict__ cols,
                          const float* __restrict__ vals, int E) {
    int base = (blockIdx.x * blockDim.x + threadIdx.x) * 4;
    #pragma unroll
    for (int q = 0; q < 4; q++) {
        int e = base + q;
        if (e < E) {
            int r = rows[e];
            int p = atomicAdd(&g_cursor[r], 1);
            g_colsorted[p] = cols[e];
            g_valsorted[p] = vals[e];
        }
    }
}

// ---------------- fp32 -> bf16 hi/lo split (with row padding) --------------------
__global__ void k_split_pad(const float* __restrict__ in, __nv_bfloat16* __restrict__ hi,
                            __nv_bfloat16* __restrict__ lo, int rows, int cols, int rows_pad) {
    size_t i4 = (size_t)blockIdx.x * blockDim.x + threadIdx.x;
    size_t total4 = (size_t)rows_pad * cols / 4;
    if (i4 >= total4) return;
    size_t i = i4 * 4;
    int r = (int)(i / cols);
    float4 v = (r < rows) ? *reinterpret_cast<const float4*>(in + i)
                          : make_float4(0.f, 0.f, 0.f, 0.f);
    uint2 hp, lp;
    split2(v.x, v.y, hp.x, lp.x);
    split2(v.z, v.w, hp.y, lp.y);
    *reinterpret_cast<uint2*>(hi + i) = hp;
    *reinterpret_cast<uint2*>(lo + i) = lp;
}

// ---------------- transpose + split: W[K,N] -> T[N,K] bf16 hi/lo ------------------
__global__ void k_transpose_split(const float* __restrict__ W, __nv_bfloat16* __restrict__ Thi,
                                  __nv_bfloat16* __restrict__ Tlo, int K, int N) {
    int i = blockIdx.x * blockDim.x + threadIdx.x;
    if (i >= K * N) return;
    int k = i / N, n = i % N;
    float v = W[i];
    __nv_bfloat16 h = __float2bfloat16(v);
    __nv_bfloat16 l = __float2bfloat16(v - __bfloat162float(h));
    Thi[(size_t)n * K + k] = h;
    Tlo[(size_t)n * K + k] = l;
}

// ---------------- split-bf16 GEMM via mma.sync (pre-split A), optional bias --------
// 256 threads, 8 warps (4m x 2n), warp tile 32 x BN/2; BK=32, 3-stage cp.async.
template<int BN, int K_TOT, int N_TOT, typename TOUT>
__global__ void __launch_bounds__(256, 1) gemm_mma(
    const __nv_bfloat16* __restrict__ Ahi, const __nv_bfloat16* __restrict__ Alo,
    const __nv_bfloat16* __restrict__ Bhi, const __nv_bfloat16* __restrict__ Blo,
    const float* __restrict__ bias,
    TOUT* __restrict__ C, int Mrows)
{
    constexpr int NC = K_TOT / 32;
    constexpr int SS = 16384 + BN * 128;
    constexpr int NT16 = BN / 32;
    constexpr int NT8  = BN / 16;

    extern __shared__ __align__(128) char smem[];
    const uint32_t sb = smem_to_u32(smem);
    const int tid = threadIdx.x;
    const int wid = tid >> 5, lane = tid & 31;
    const int warpM = wid & 3, warpN = wid >> 2;
    const int m0 = blockIdx.x * 128;
    const int n_off = blockIdx.y * BN;
    const int wm0 = warpM * 32;
    const int wn0 = warpN * (BN / 2);

    float acc[2][NT8][4];
    #pragma unroll
    for (int i = 0; i < 2; i++)
        #pragma unroll
        for (int j = 0; j < NT8; j++)
            #pragma unroll
            for (int q = 0; q < 4; q++) acc[i][j][q] = 0.f;

    auto load_chunk = [&](int kc) {
        const uint32_t sd = sb + (uint32_t)(kc % 3) * SS;
        #pragma unroll
        for (int i = tid; i < 1024; i += 256) {
            int buf = i >> 9, idx = i & 511;
            int r = idx >> 2, c16 = idx & 3;
            uint32_t dst = sd + (uint32_t)buf * 8192 + swz(r, c16);
            const char* g = (const char*)((buf ? Alo : Ahi) + (size_t)(m0 + r) * K_TOT)
                            + kc * 64 + c16 * 16;
            CP_ASYNC16(dst, g);
        }
        #pragma unroll
        for (int i = tid; i < 2 * BN * 4; i += 256) {
            int buf = (i >= BN * 4);
            int idx = buf ? i - BN * 4 : i;
            int r = idx >> 2, c16 = idx & 3;
            uint32_t dst = sd + 16384 + (uint32_t)buf * (BN * 64) + swz(r, c16);
            const char* g = (const char*)((buf ? Blo : Bhi) + (size_t)(n_off + r) * K_TOT)
                            + kc * 64 + c16 * 16;
            CP_ASYNC16(dst, g);
        }
        CP_COMMIT();
    };

    load_chunk(0);
    if (NC > 1) load_chunk(1);

    for (int kc = 0; kc < NC; kc++) {
        if (kc + 1 < NC) { CP_WAIT(1); } else { CP_WAIT(0); }
        __syncthreads();
        if (kc + 2 < NC) load_chunk(kc + 2);

        const uint32_t sA_hi = sb + (uint32_t)(kc % 3) * SS;
        const uint32_t sA_lo = sA_hi + 8192;
        const uint32_t sB_hi = sA_lo + 8192;
        const uint32_t sB_lo = sB_hi + BN * 64;

        #pragma unroll
        for (int ks = 0; ks < 2; ks++) {
            uint32_t ahi[2][4], alo[2][4];
            #pragma unroll
            for (int mt = 0; mt < 2; mt++) {
                int row = wm0 + mt * 16 + (lane & 15);
                int c16 = ks * 2 + (lane >> 4);
                LDSM_X4(ahi[mt], sA_hi + swz(row, c16));
                LDSM_X4(alo[mt], sA_lo + swz(row, c16));
            }
            uint32_t bhi[NT16][4], blo[NT16][4];
            #pragma unroll
            for (int g = 0; g < NT16; g++) {
                int row = wn0 + g * 16 + (lane & 15);
                int c16 = ks * 2 + (lane >> 4);
                LDSM_X4(bhi[g], sB_hi + swz(row, c16));
                LDSM_X4(blo[g], sB_lo + swz(row, c16));
            }
            #pragma unroll
            for (int mt = 0; mt < 2; mt++)
                #pragma unroll
                for (int g = 0; g < NT16; g++)
                    #pragma unroll
                    for (int h = 0; h < 2; h++) {
                        int nt = g * 2 + h;
                        mma16816(acc[mt][nt], ahi[mt], bhi[g][h], bhi[g][2 + h]);
                        mma16816(acc[mt][nt], alo[mt], bhi[g][h], bhi[g][2 + h]);
                        mma16816(acc[mt][nt], ahi[mt], blo[g][h], blo[g][2 + h]);
                    }
        }
        __syncthreads();
    }

    #pragma unroll
    for (int mt = 0; mt < 2; mt++) {
        int m = m0 + wm0 + mt * 16 + (lane >> 2);
        #pragma unroll
        for (int nt = 0; nt < NT8; nt++) {
            int n = n_off + wn0 + nt * 8 + (lane & 3) * 2;
            float bx = 0.f, by = 0.f;
            if (bias) {
                float2 bv = *reinterpret_cast<const float2*>(bias + n);
                bx = bv.x; by = bv.y;
            }
            if (m < Mrows)
                store2(C + (size_t)m * N_TOT + n, acc[mt][nt][0] + bx, acc[mt][nt][1] + by);
            if (m + 8 < Mrows)
                store2(C + (size_t)(m + 8) * N_TOT + n, acc[mt][nt][2] + bx, acc[mt][nt][3] + by);
        }
    }
}

// ---------------- SpMM over sorted CSR, fp16 gather -------------------------------
// spmm1: h = relu(spmm(adj, XW1h) + b1) -> hi/lo bf16.  F=256: 32 threads/row.
template<int F>
__global__ void spmm1_fp16(const __half* __restrict__ src, const float* __restrict__ bias,
                           __nv_bfloat16* __restrict__ hi, __nv_bfloat16* __restrict__ lo,
                           int nrows) {
    constexpr int TPR = F / 8;              // 8 halves (16B) per thread
    constexpr int RPB = 256 / TPR;
    const int lane = threadIdx.x % TPR;
    const int row  = blockIdx.x * RPB + threadIdx.x / TPR;
    if (row >= nrows) return;

    const int s = g_rowptr[row];
    const int e = g_rowptr[row + 1];
    float acc[8];
    #pragma unroll
    for (int q = 0; q < 8; q++) acc[q] = 0.f;

    const size_t loff = (size_t)lane * 8;
    for (int j = s; j < e; j++) {
        int   c = g_colsorted[j];
        float v = g_valsorted[j];
        uint4 r = *reinterpret_cast<const uint4*>(src + (size_t)c * F + loff);
        float2 f0 = __half22float2(*reinterpret_cast<__half2*>(&r.x));
        float2 f1 = __half22float2(*reinterpret_cast<__half2*>(&r.y));
        float2 f2 = __half22float2(*reinterpret_cast<__half2*>(&r.z));
        float2 f3 = __half22float2(*reinterpret_cast<__half2*>(&r.w));
        acc[0] = fmaf(v, f0.x, acc[0]); acc[1] = fmaf(v, f0.y, acc[1]);
        acc[2] = fmaf(v, f1.x, acc[2]); acc[3] = fmaf(v, f1.y, acc[3]);
        acc[4] = fmaf(v, f2.x, acc[4]); acc[5] = fmaf(v, f2.y, acc[5]);
        acc[6] = fmaf(v, f3.x, acc[6]); acc[7] = fmaf(v, f3.y, acc[7]);
    }
    float4 b0 = *reinterpret_cast<const float4*>(bias + loff);
    float4 b1 = *reinterpret_cast<const float4*>(bias + loff + 4);
    acc[0] = fmaxf(acc[0] + b0.x, 0.f); acc[1] = fmaxf(acc[1] + b0.y, 0.f);
    acc[2] = fmaxf(acc[2] + b0.z, 0.f); acc[3] = fmaxf(acc[3] + b0.w, 0.f);
    acc[4] = fmaxf(acc[4] + b1.x, 0.f); acc[5] = fmaxf(acc[5] + b1.y, 0.f);
    acc[6] = fmaxf(acc[6] + b1.z, 0.f); acc[7] = fmaxf(acc[7] + b1.w, 0.f);

    uint4 hv, lv;
    split2(acc[0], acc[1], hv.x, lv.x);
    split2(acc[2], acc[3], hv.y, lv.y);
    split2(acc[4], acc[5], hv.z, lv.z);
    split2(acc[6], acc[7], hv.w, lv.w);
    size_t off = (size_t)row * F + loff;
    *reinterpret_cast<uint4*>(hi + off) = hv;
    *reinterpret_cast<uint4*>(lo + off) = lv;
}

// spmm2: z = spmm(adj, HW2h) + b2 (fp32) + relu(z) split hi/lo.  F=64: 8 threads/row.
template<int F>
__global__ void spmm2_fp16(const __half* __restrict__ src, const float* __restrict__ bias,
                           float* __restrict__ z,
                           __nv_bfloat16* __restrict__ zhi, __nv_bfloat16* __restrict__ zlo,
                           int nrows) {
    constexpr int TPR = F / 8;
    constexpr int RPB = 256 / TPR;
    const int lane = threadIdx.x % TPR;
    const int row  = blockIdx.x * RPB + threadIdx.x / TPR;
    if (row >= nrows) return;

    const int s = g_rowptr[row];
    const int e = g_rowptr[row + 1];
    float acc[8];
    #pragma unroll
    for (int q = 0; q < 8; q++) acc[q] = 0.f;

    const size_t loff = (size_t)lane * 8;
    for (int j = s; j < e; j++) {
        int   c = g_colsorted[j];
        float v = g_valsorted[j];
        uint4 r = *reinterpret_cast<const uint4*>(src + (size_t)c * F + loff);
        float2 f0 = __half22float2(*reinterpret_cast<__half2*>(&r.x));
        float2 f1 = __half22float2(*reinterpret_cast<__half2*>(&r.y));
        float2 f2 = __half22float2(*reinterpret_cast<__half2*>(&r.z));
        float2 f3 = __half22float2(*reinterpret_cast<__half2*>(&r.w));
        acc[0] = fmaf(v, f0.x, acc[0]); acc[1] = fmaf(v, f0.y, acc[1]);
        acc[2] = fmaf(v, f1.x, acc[2]); acc[3] = fmaf(v, f1.y, acc[3]);
        acc[4] = fmaf(v, f2.x, acc[4]); acc[5] = fmaf(v, f2.y, acc[5]);
        acc[6] = fmaf(v, f3.x, acc[6]); acc[7] = fmaf(v, f3.y, acc[7]);
    }
    float4 b0 = *reinterpret_cast<const float4*>(bias + loff);
    float4 b1 = *reinterpret_cast<const float4*>(bias + loff + 4);
    acc[0] += b0.x; acc[1] += b0.y; acc[2] += b0.z; acc[3] += b0.w;
    acc[4] += b1.x; acc[5] += b1.y; acc[6] += b1.z; acc[7] += b1.w;

    size_t off = (size_t)row * F + loff;
    *reinterpret_cast<float4*>(z + off)     = make_float4(acc[0], acc[1], acc[2], acc[3]);
    *reinterpret_cast<float4*>(z + off + 4) = make_float4(acc[4], acc[5], acc[6], acc[7]);

    uint4 hv, lv;
    split2(fmaxf(acc[0], 0.f), fmaxf(acc[1], 0.f), hv.x, lv.x);
    split2(fmaxf(acc[2], 0.f), fmaxf(acc[3], 0.f), hv.y, lv.y);
    split2(fmaxf(acc[4], 0.f), fmaxf(acc[5], 0.f), hv.z, lv.z);
    split2(fmaxf(acc[6], 0.f), fmaxf(acc[7], 0.f), hv.w, lv.w);
    *reinterpret_cast<uint4*>(zhi + off) = hv;
    *reinterpret_cast<uint4*>(zlo + off) = lv;
}

// ---------------- log_softmax over 64 classes --------------------------------------
__global__ void k_logsoftmax(const float* __restrict__ z, float* __restrict__ out, int nrows) {
    int row  = blockIdx.x * 8 + threadIdx.x / 32;
    int lane = threadIdx.x & 31;
    if (row >= nrows) return;
    float2 v = *reinterpret_cast<const float2*>(z + (size_t)row * F_CLS + lane * 2);
    float m = fmaxf(v.x, v.y);
    #pragma unroll
    for (int off = 16; off; off >>= 1) m = fmaxf(m, __shfl_xor_sync(0xffffffffu, m, off));
    float s = expf(v.x - m) + expf(v.y - m);
    #pragma unroll
    for (int off = 16; off; off >>= 1) s += __shfl_xor_sync(0xffffffffu, s, off);
    float ls = m + logf(s);
    float2 o; o.x = v.x - ls; o.y = v.y - ls;
    *reinterpret_cast<float2*>(out + (size_t)row * F_CLS + lane * 2) = o;
}

// ---------------- launch ------------------------------------------------------------
extern "C" void kernel_launch(void* const* d_in, const int* in_sizes, int n_in,
                              void* d_out, int out_size) {
    const float* x    = (const float*)d_in[0];
    const float* vals = (const float*)d_in[1];
    const float* W1   = (const float*)d_in[2];
    const float* b1   = (const float*)d_in[3];
    const float* W2   = (const float*)d_in[4];
    const float* b2   = (const float*)d_in[5];
    const float* W3   = (const float*)d_in[6];
    const float* b3   = (const float*)d_in[7];
    const int*   rows = (const int*)d_in[8];
    const int*   cols = (const int*)d_in[9];

    const int E = in_sizes[8];
    const int M = in_sizes[0] / F_IN;   // 100000

    float* out1 = (float*)d_out;                      // log_softmax [M, 64]
    float* out2 = (float*)d_out + (size_t)M * F_CLS;  // projection  [M, 128]

    float* pz;
    __half *pXW1h, *pHW2h;
    __nv_bfloat16 *pxhi, *pxlo, *phhi, *phlo, *pzhi, *pzlo;
    __nv_bfloat16 *pw1thi, *pw1tlo, *pw2thi, *pw2tlo, *pw3thi, *pw3tlo;
    cudaGetSymbolAddress((void**)&pXW1h, g_XW1h);
    cudaGetSymbolAddress((void**)&pHW2h, g_HW2h);
    cudaGetSymbolAddress((void**)&pz,    g_z);
    cudaGetSymbolAddress((void**)&pxhi,  g_xhi);
    cudaGetSymbolAddress((void**)&pxlo,  g_xlo);
    cudaGetSymbolAddress((void**)&phhi,  g_hhi);
    cudaGetSymbolAddress((void**)&phlo,  g_hlo);
    cudaGetSymbolAddress((void**)&pzhi,  g_zhi);
    cudaGetSymbolAddress((void**)&pzlo,  g_zlo);
    cudaGetSymbolAddress((void**)&pw1thi, g_w1thi);
    cudaGetSymbolAddress((void**)&pw1tlo, g_w1tlo);
    cudaGetSymbolAddress((void**)&pw2thi, g_w2thi);
    cudaGetSymbolAddress((void**)&pw2tlo, g_w2tlo);
    cudaGetSymbolAddress((void**)&pw3thi, g_w3thi);
    cudaGetSymbolAddress((void**)&pw3tlo, g_w3tlo);

    constexpr int SMEM1 = 3 * (16384 + 128 * 128);  // gemm1: 98304
    constexpr int SMEM2 = 3 * (16384 + 64 * 128);   // gemm2: 73728
    constexpr int SMEM3 = 3 * (16384 + 128 * 128);  // gemm3: 98304
    cudaFuncSetAttribute(gemm_mma<128, F_IN, F_HID, __half>,
                         cudaFuncAttributeMaxDynamicSharedMemorySize, SMEM1);
    cudaFuncSetAttribute(gemm_mma<64, F_HID, F_CLS, __half>,
                         cudaFuncAttributeMaxDynamicSharedMemorySize, SMEM2);
    cudaFuncSetAttribute(gemm_mma<128, F_CLS, F_PROJ, float>,
                         cudaFuncAttributeMaxDynamicSharedMemorySize, SMEM3);

    const int MT = NN_PAD / 128;  // 782 row tiles

    // 1) bucket edges into CSR (reused by both spmms)
    k_zero_counts<<<(M + 255) / 256, 256>>>(M);
    k_hist<<<(E + 1023) / 1024, 256>>>(rows, E);
    k_scan<<<1, 1024>>>(M);
    k_scatter<<<(E + 1023) / 1024, 256>>>(rows, cols, vals, E);

    // 2) split conversions
    {
        size_t total4 = (size_t)NN_PAD * F_IN / 4;
        k_split_pad<<<(unsigned)((total4 + 255) / 256), 256>>>(x, pxhi, pxlo, M, F_IN, NN_PAD);
    }
    k_transpose_split<<<(F_IN * F_HID + 255) / 256, 256>>>(W1, pw1thi, pw1tlo, F_IN, F_HID);
    k_transpose_split<<<(F_HID * F_CLS + 255) / 256, 256>>>(W2, pw2thi, pw2tlo, F_HID, F_CLS);
    k_transpose_split<<<(F_CLS * F_PROJ + 255) / 256, 256>>>(W3, pw3thi, pw3tlo, F_CLS, F_PROJ);

    // 3) XW1 = x @ W1 (tensor cores, split-bf16, fp16 out)
    gemm_mma<128, F_IN, F_HID, __half><<<dim3(MT, 2), 256, SMEM1>>>(
        pxhi, pxlo, pw1thi, pw1tlo, nullptr, pXW1h, M);

    // 4) h = relu(spmm(adj, XW1) + b1) -> bf16 hi/lo (fp16 gather)
    spmm1_fp16<F_HID><<<(M + 7) / 8, 256>>>(pXW1h, b1, phhi, phlo, M);

    // 5) HW2 = h @ W2 (tensor cores, fp16 out)
    gemm_mma<64, F_HID, F_CLS, __half><<<dim3(MT, 1), 256, SMEM2>>>(
        phhi, phlo, pw2thi, pw2tlo, nullptr, pHW2h, M);

    // 6) z = spmm(adj, HW2) + b2 (fp16 gather); relu(z) split for GEMM3
    spmm2_fp16<F_CLS><<<(M + 31) / 32, 256>>>(pHW2h, b2, pz, pzhi, pzlo, M);

    // 7) out1 = log_softmax(z)
    k_logsoftmax<<<(M + 7) / 8, 256>>>(pz, out1, M);

    // 8) out2 = relu(z) @ W3 + b3 (tensor cores, fp32 out + bias)
    gemm_mma<128, F_CLS, F_PROJ, float><<<dim3(MT, 1), 256, SMEM3>>>(
        pzhi, pzlo, pw3thi, pw3tlo, b3, out2, M);
}

// round 6
// speedup vs baseline: 1.9150x; 1.0275x over previous
#include <cuda_runtime.h>
#include <cuda_bf16.h>
#include <cuda_fp16.h>
#include <cstdint>

#define NN 100000
#define NN_PAD 100096      // 782 * 128
#define NE_MAX 3400000
#define F_IN   512
#define F_HID  256
#define F_CLS  64
#define F_PROJ 128

// ---------------- scratch (static device globals; no allocation) ----------------
__device__ __half g_XW1h[(size_t)NN * F_HID];   // x @ W1 (fp16)
__device__ __half g_HW2h[(size_t)NN * F_CLS];   // h @ W2 (fp16)
__device__ __nv_bfloat16 g_hhi[(size_t)NN_PAD * F_HID];
__device__ __nv_bfloat16 g_hlo[(size_t)NN_PAD * F_HID];
__device__ __nv_bfloat16 g_zhi[(size_t)NN_PAD * F_CLS];   // relu(z) split
__device__ __nv_bfloat16 g_zlo[(size_t)NN_PAD * F_CLS];
__device__ __nv_bfloat16 g_w1thi[F_HID * F_IN];   // W1^T [256,512]
__device__ __nv_bfloat16 g_w1tlo[F_HID * F_IN];
__device__ __nv_bfloat16 g_w2thi[F_CLS * F_HID];  // W2^T [64,256]
__device__ __nv_bfloat16 g_w2tlo[F_CLS * F_HID];
__device__ __nv_bfloat16 g_w3thi[F_PROJ * F_CLS]; // W3^T [128,64]
__device__ __nv_bfloat16 g_w3tlo[F_PROJ * F_CLS];
__device__ int   g_counts[NN];
__device__ int   g_rowptr[NN + 1];
__device__ int   g_cursor[NN];
__device__ int2  g_edges[NE_MAX];   // (col, val-as-int) packed
__device__ float g_dummy;

// ---------------- PTX helpers (sm_103-safe; no tcgen05) ---------------------------
__device__ __forceinline__ uint32_t smem_to_u32(const void* p) {
    uint32_t a;
    asm("{ .reg .u64 t; cvta.to.shared.u64 t, %1; cvt.u32.u64 %0, t; }" : "=r"(a) : "l"(p));
    return a;
}
#define CP_ASYNC16(dst, src) \
    asm volatile("cp.async.cg.shared.global [%0], [%1], 16;" :: "r"(dst), "l"(src))
#define CP_ASYNC16_Z(dst, src, sz) \
    asm volatile("cp.async.cg.shared.global [%0], [%1], 16, %2;" :: "r"(dst), "l"(src), "r"(sz))
#define CP_COMMIT() asm volatile("cp.async.commit_group;" ::: "memory")
#define CP_WAIT(N)  asm volatile("cp.async.wait_group %0;" :: "n"(N) : "memory")

#define LDSM_X4(r, addr) \
    asm volatile("ldmatrix.sync.aligned.m8n8.x4.shared.b16 {%0,%1,%2,%3}, [%4];" \
        : "=r"((r)[0]), "=r"((r)[1]), "=r"((r)[2]), "=r"((r)[3]) : "r"(addr))

__device__ __forceinline__ void mma16816(float* c, const uint32_t* a, uint32_t b0, uint32_t b1) {
    asm volatile("mma.sync.aligned.m16n8k16.row.col.f32.bf16.bf16.f32 "
        "{%0,%1,%2,%3}, {%4,%5,%6,%7}, {%8,%9}, {%0,%1,%2,%3};"
        : "+f"(c[0]), "+f"(c[1]), "+f"(c[2]), "+f"(c[3])
        : "r"(a[0]), "r"(a[1]), "r"(a[2]), "r"(a[3]), "r"(b0), "r"(b1));
}

// XOR swizzle for 64B-row tiles: row r, 16B-column c16 (0..3)
__device__ __forceinline__ uint32_t swz(int r, int c16) {
    return (uint32_t)(r * 64 + ((c16 ^ ((r >> 1) & 3)) << 4));
}

// pack 2 floats -> hi bf16x2 + lo bf16x2 (residual)
__device__ __forceinline__ void split2(float a, float b, uint32_t& hi, uint32_t& lo) {
    __nv_bfloat16 ha = __float2bfloat16(a), hb = __float2bfloat16(b);
    __nv_bfloat16 la = __float2bfloat16(a - __bfloat162float(ha));
    __nv_bfloat16 lb = __float2bfloat16(b - __bfloat162float(hb));
    __nv_bfloat162 h; h.x = ha; h.y = hb;
    __nv_bfloat162 l; l.x = la; l.y = lb;
    hi = *(uint32_t*)&h;
    lo = *(uint32_t*)&l;
}

// epilogue store helpers (fp32 or fp16 output)
__device__ __forceinline__ void store2(float* p, float x, float y) {
    *reinterpret_cast<float2*>(p) = make_float2(x, y);
}
__device__ __forceinline__ void store2(__half* p, float x, float y) {
    *reinterpret_cast<__half2*>(p) = __floats2half2_rn(x, y);
}

// ---------------- edge bucketing --------------------------------------------------
__global__ void k_zero_counts(int n) {
    int i = blockIdx.x * blockDim.x + threadIdx.x;
    if (i < n) g_counts[i] = 0;
}
__global__ void k_hist(const int* __restrict__ rows, int E) {
    int base = (blockIdx.x * blockDim.x + threadIdx.x) * 4;
    #pragma unroll
    for (int q = 0; q < 4; q++) {
        int e = base + q;
        if (e < E) atomicAdd(&g_counts[rows[e]], 1);
    }
}
__global__ void k_scan(int n) {
    __shared__ int part[1024];
    int tid = threadIdx.x;
    int per = (n + 1023) >> 10;
    int st = tid * per;
    int en = st + per; if (en > n) en = n;
    int s = 0;
    for (int i = st; i < en; i++) s += g_counts[i];
    part[tid] = s;
    __syncthreads();
    #pragma unroll
    for (int off = 1; off < 1024; off <<= 1) {
        int v = (tid >= off) ? part[tid - off] : 0;
        __syncthreads();
        part[tid] += v;
        __syncthreads();
    }
    int base = (tid == 0) ? 0 : part[tid - 1];
    for (int i = st; i < en; i++) {
        int c = g_counts[i];
        g_rowptr[i] = base;
        g_cursor[i] = base;
        base += c;
    }
    if (tid == 1023) g_rowptr[n] = part[1023];
}
__global__ void k_scatter(const int* __restrict__ rows, const int* __restrict__ cols,
                          const float* __restrict__ vals, int E) {
    int base = (blockIdx.x * blockDim.x + threadIdx.x) * 4;
    #pragma unroll
    for (int q = 0; q < 4; q++) {
        int e = base + q;
        if (e < E) {
            int r = rows[e];
            int p = atomicAdd(&g_cursor[r], 1);
            g_edges[p] = make_int2(cols[e], __float_as_int(vals[e]));
        }
    }
}

// ---------------- transpose + split: W[K,N] -> T[N,K] bf16 hi/lo ------------------
__global__ void k_transpose_split(const float* __restrict__ W, __nv_bfloat16* __restrict__ Thi,
                                  __nv_bfloat16* __restrict__ Tlo, int K, int N) {
    int i = blockIdx.x * blockDim.x + threadIdx.x;
    if (i >= K * N) return;
    int k = i / N, n = i % N;
    float v = W[i];
    __nv_bfloat16 h = __float2bfloat16(v);
    __nv_bfloat16 l = __float2bfloat16(v - __bfloat162float(h));
    Thi[(size_t)n * K + k] = h;
    Tlo[(size_t)n * K + k] = l;
}

// ---------------- GEMM1: XW1h[M,256] = x[M,512] @ W1, fused fp32->hi/lo split ------
// 512 threads, 16 warps (4m x 4n), warp tile 32x64 (NT16=4 B groups). BK=32.
__global__ void __launch_bounds__(512, 1) gemm1_fused(
    const float* __restrict__ X,
    const __nv_bfloat16* __restrict__ Bhi, const __nv_bfloat16* __restrict__ Blo,
    __half* __restrict__ C, int Mrows)
{
    constexpr int K_TOT = 512, N_TOT = 256, NC = 16;
    constexpr int SS = 65536;
    constexpr int OFF_X = 0, OFF_AH = 16384, OFF_AL = 24576, OFF_BH = 32768, OFF_BL = 49152;

    extern __shared__ __align__(128) char smem[];
    const uint32_t sb = smem_to_u32(smem);
    const int tid = threadIdx.x;
    const int wid = tid >> 5, lane = tid & 31;
    const int warpM = wid & 3, warpN = wid >> 2;
    const int m0 = blockIdx.x * 128;
    const int wm0 = warpM * 32, wn0 = warpN * 64;

    float acc[2][8][4];
    #pragma unroll
    for (int i = 0; i < 2; i++)
        #pragma unroll
        for (int j = 0; j < 8; j++)
            #pragma unroll
            for (int q = 0; q < 4; q++) acc[i][j][q] = 0.f;

    auto load_chunk = [&](int kc) {
        const uint32_t sd = sb + (uint32_t)(kc % 3) * SS;
        // x fp32: 128 rows x 128B -> 1024 16B units, linear
        #pragma unroll
        for (int i = tid; i < 1024; i += 512) {
            int r = i >> 3, c = i & 7;
            uint32_t dst = sd + OFF_X + (uint32_t)i * 16;
            int rr = m0 + r;
            uint32_t sz = (rr < Mrows) ? 16u : 0u;
            if (rr >= Mrows) rr = m0;   // keep address in-bounds; sz=0 zero-fills
            const char* g = (const char*)(X + (size_t)rr * K_TOT + kc * 32) + c * 16;
            CP_ASYNC16_Z(dst, g, sz);
        }
        // B hi+lo: 2 x 256 rows x 4 16B units, swizzled
        #pragma unroll
        for (int i = tid; i < 2048; i += 512) {
            int buf = i >> 10, idx = i & 1023;
            int r = idx >> 2, c16 = idx & 3;
            uint32_t dst = sd + OFF_BH + (uint32_t)buf * 16384 + swz(r, c16);
            const char* g = (const char*)((buf ? Blo : Bhi) + (size_t)r * K_TOT + kc * 32)
                            + c16 * 16;
            CP_ASYNC16(dst, g);
        }
        CP_COMMIT();
    };

    load_chunk(0);
    load_chunk(1);

    for (int kc = 0; kc < NC; kc++) {
        if (kc + 1 < NC) { CP_WAIT(1); } else { CP_WAIT(0); }
        __syncthreads();

        char* basep = smem + (size_t)(kc % 3) * SS;
        // convert x fp32 -> swizzled hi/lo bf16 (thread t: row t>>2, 16B-unit t&3)
        {
            int r = tid >> 2, c16 = tid & 3;
            float4 f0 = *reinterpret_cast<const float4*>(basep + OFF_X + (size_t)tid * 32);
            float4 f1 = *reinterpret_cast<const float4*>(basep + OFF_X + (size_t)tid * 32 + 16);
            uint4 hv, lv;
            split2(f0.x, f0.y, hv.x, lv.x);
            split2(f0.z, f0.w, hv.y, lv.y);
            split2(f1.x, f1.y, hv.z, lv.z);
            split2(f1.z, f1.w, hv.w, lv.w);
            *reinterpret_cast<uint4*>(basep + OFF_AH + swz(r, c16)) = hv;
            *reinterpret_cast<uint4*>(basep + OFF_AL + swz(r, c16)) = lv;
        }
        __syncthreads();

        if (kc + 2 < NC) load_chunk(kc + 2);

        const uint32_t sA_hi = sb + (uint32_t)(kc % 3) * SS + OFF_AH;
        const uint32_t sA_lo = sA_hi + 8192;
        const uint32_t sB_hi = sb + (uint32_t)(kc % 3) * SS + OFF_BH;
        const uint32_t sB_lo = sB_hi + 16384;

        #pragma unroll
        for (int ks = 0; ks < 2; ks++) {
            uint32_t ahi[2][4], alo[2][4];
            #pragma unroll
            for (int mt = 0; mt < 2; mt++) {
                int row = wm0 + mt * 16 + (lane & 15);
                int c16 = ks * 2 + (lane >> 4);
                LDSM_X4(ahi[mt], sA_hi + swz(row, c16));
                LDSM_X4(alo[mt], sA_lo + swz(row, c16));
            }
            #pragma unroll
            for (int g = 0; g < 4; g++) {          // 4 B-groups = full 64-wide warp tile
                uint32_t bhi[4], blo[4];
                int row = wn0 + g * 16 + (lane & 15);
                int c16 = ks * 2 + (lane >> 4);
                LDSM_X4(bhi, sB_hi + swz(row, c16));
                LDSM_X4(blo, sB_lo + swz(row, c16));
                #pragma unroll
                for (int mt = 0; mt < 2; mt++)
                    #pragma unroll
                    for (int h = 0; h < 2; h++) {
                        int nt = g * 2 + h;
                        mma16816(acc[mt][nt], ahi[mt], bhi[h], bhi[2 + h]);
                        mma16816(acc[mt][nt], alo[mt], bhi[h], bhi[2 + h]);
                        mma16816(acc[mt][nt], ahi[mt], blo[h], blo[2 + h]);
                    }
            }
        }
        __syncthreads();
    }

    #pragma unroll
    for (int mt = 0; mt < 2; mt++) {
        int m = m0 + wm0 + mt * 16 + (lane >> 2);
        #pragma unroll
        for (int nt = 0; nt < 8; nt++) {
            int n = wn0 + nt * 8 + (lane & 3) * 2;
            if (m < Mrows)
                store2(C + (size_t)m * N_TOT + n, acc[mt][nt][0], acc[mt][nt][1]);
            if (m + 8 < Mrows)
                store2(C + (size_t)(m + 8) * N_TOT + n, acc[mt][nt][2], acc[mt][nt][3]);
        }
    }
}

// ---------------- split-bf16 GEMM via mma.sync (pre-split A), optional bias --------
// 256 threads, 8 warps (4m x 2n), warp tile 32 x BN/2; BK=32, 3-stage cp.async.
template<int BN, int K_TOT, int N_TOT, typename TOUT>
__global__ void __launch_bounds__(256, 1) gemm_mma(
    const __nv_bfloat16* __restrict__ Ahi, const __nv_bfloat16* __restrict__ Alo,
    const __nv_bfloat16* __restrict__ Bhi, const __nv_bfloat16* __restrict__ Blo,
    const float* __restrict__ bias,
    TOUT* __restrict__ C, int Mrows)
{
    constexpr int NC = K_TOT / 32;
    constexpr int SS = 16384 + BN * 128;
    constexpr int NT16 = BN / 32;
    constexpr int NT8  = BN / 16;

    extern __shared__ __align__(128) char smem[];
    const uint32_t sb = smem_to_u32(smem);
    const int tid = threadIdx.x;
    const int wid = tid >> 5, lane = tid & 31;
    const int warpM = wid & 3, warpN = wid >> 2;
    const int m0 = blockIdx.x * 128;
    const int n_off = blockIdx.y * BN;
    const int wm0 = warpM * 32;
    const int wn0 = warpN * (BN / 2);

    float acc[2][NT8][4];
    #pragma unroll
    for (int i = 0; i < 2; i++)
        #pragma unroll
        for (int j = 0; j < NT8; j++)
            #pragma unroll
            for (int q = 0; q < 4; q++) acc[i][j][q] = 0.f;

    auto load_chunk = [&](int kc) {
        const uint32_t sd = sb + (uint32_t)(kc % 3) * SS;
        #pragma unroll
        for (int i = tid; i < 1024; i += 256) {
            int buf = i >> 9, idx = i & 511;
            int r = idx >> 2, c16 = idx & 3;
            uint32_t dst = sd + (uint32_t)buf * 8192 + swz(r, c16);
            const char* g = (const char*)((buf ? Alo : Ahi) + (size_t)(m0 + r) * K_TOT)
                            + kc * 64 + c16 * 16;
            CP_ASYNC16(dst, g);
        }
        #pragma unroll
        for (int i = tid; i < 2 * BN * 4; i += 256) {
            int buf = (i >= BN * 4);
            int idx = buf ? i - BN * 4 : i;
            int r = idx >> 2, c16 = idx & 3;
            uint32_t dst = sd + 16384 + (uint32_t)buf * (BN * 64) + swz(r, c16);
            const char* g = (const char*)((buf ? Blo : Bhi) + (size_t)(n_off + r) * K_TOT)
                            + kc * 64 + c16 * 16;
            CP_ASYNC16(dst, g);
        }
        CP_COMMIT();
    };

    load_chunk(0);
    if (NC > 1) load_chunk(1);

    for (int kc = 0; kc < NC; kc++) {
        if (kc + 1 < NC) { CP_WAIT(1); } else { CP_WAIT(0); }
        __syncthreads();
        if (kc + 2 < NC) load_chunk(kc + 2);

        const uint32_t sA_hi = sb + (uint32_t)(kc % 3) * SS;
        const uint32_t sA_lo = sA_hi + 8192;
        const uint32_t sB_hi = sA_lo + 8192;
        const uint32_t sB_lo = sB_hi + BN * 64;

        #pragma unroll
        for (int ks = 0; ks < 2; ks++) {
            uint32_t ahi[2][4], alo[2][4];
            #pragma unroll
            for (int mt = 0; mt < 2; mt++) {
                int row = wm0 + mt * 16 + (lane & 15);
                int c16 = ks * 2 + (lane >> 4);
                LDSM_X4(ahi[mt], sA_hi + swz(row, c16));
                LDSM_X4(alo[mt], sA_lo + swz(row, c16));
            }
            #pragma unroll
            for (int g = 0; g < NT16; g++) {
                uint32_t bhi[4], blo[4];
                int row = wn0 + g * 16 + (lane & 15);
                int c16 = ks * 2 + (lane >> 4);
                LDSM_X4(bhi, sB_hi + swz(row, c16));
                LDSM_X4(blo, sB_lo + swz(row, c16));
                #pragma unroll
                for (int mt = 0; mt < 2; mt++)
                    #pragma unroll
                    for (int h = 0; h < 2; h++) {
                        int nt = g * 2 + h;
                        mma16816(acc[mt][nt], ahi[mt], bhi[h], bhi[2 + h]);
                        mma16816(acc[mt][nt], alo[mt], bhi[h], bhi[2 + h]);
                        mma16816(acc[mt][nt], ahi[mt], blo[h], blo[2 + h]);
                    }
            }
        }
        __syncthreads();
    }

    #pragma unroll
    for (int mt = 0; mt < 2; mt++) {
        int m = m0 + wm0 + mt * 16 + (lane >> 2);
        #pragma unroll
        for (int nt = 0; nt < NT8; nt++) {
            int n = n_off + wn0 + nt * 8 + (lane & 3) * 2;
            float bx = 0.f, by = 0.f;
            if (bias) {
                float2 bv = *reinterpret_cast<const float2*>(bias + n);
                bx = bv.x; by = bv.y;
            }
            if (m < Mrows)
                store2(C + (size_t)m * N_TOT + n, acc[mt][nt][0] + bx, acc[mt][nt][1] + by);
            if (m + 8 < Mrows)
                store2(C + (size_t)(m + 8) * N_TOT + n, acc[mt][nt][2] + bx, acc[mt][nt][3] + by);
        }
    }
}

// ---------------- SpMM over sorted CSR, fp16 gather -------------------------------
// spmm1: h = relu(spmm(adj, XW1h) + b1) -> hi/lo bf16.  F=256: 32 threads/row.
template<int F>
__global__ void spmm1_fp16(const __half* __restrict__ src, const float* __restrict__ bias,
                           __nv_bfloat16* __restrict__ hi, __nv_bfloat16* __restrict__ lo,
                           int nrows) {
    constexpr int TPR = F / 8;              // 8 halves (16B) per thread
    constexpr int RPB = 256 / TPR;
    const int lane = threadIdx.x % TPR;
    const int row  = blockIdx.x * RPB + threadIdx.x / TPR;
    if (row >= nrows) return;

    const int s = g_rowptr[row];
    const int e = g_rowptr[row + 1];
    float acc[8];
    #pragma unroll
    for (int q = 0; q < 8; q++) acc[q] = 0.f;

    const size_t loff = (size_t)lane * 8;
    for (int j = s; j < e; j++) {
        int2  ev = g_edges[j];
        float v  = __int_as_float(ev.y);
        uint4 r = *reinterpret_cast<const uint4*>(src + (size_t)ev.x * F + loff);
        float2 f0 = __half22float2(*reinterpret_cast<__half2*>(&r.x));
        float2 f1 = __half22float2(*reinterpret_cast<__half2*>(&r.y));
        float2 f2 = __half22float2(*reinterpret_cast<__half2*>(&r.z));
        float2 f3 = __half22float2(*reinterpret_cast<__half2*>(&r.w));
        acc[0] = fmaf(v, f0.x, acc[0]); acc[1] = fmaf(v, f0.y, acc[1]);
        acc[2] = fmaf(v, f1.x, acc[2]); acc[3] = fmaf(v, f1.y, acc[3]);
        acc[4] = fmaf(v, f2.x, acc[4]); acc[5] = fmaf(v, f2.y, acc[5]);
        acc[6] = fmaf(v, f3.x, acc[6]); acc[7] = fmaf(v, f3.y, acc[7]);
    }
    float4 b0 = *reinterpret_cast<const float4*>(bias + loff);
    float4 b1 = *reinterpret_cast<const float4*>(bias + loff + 4);
    acc[0] = fmaxf(acc[0] + b0.x, 0.f); acc[1] = fmaxf(acc[1] + b0.y, 0.f);
    acc[2] = fmaxf(acc[2] + b0.z, 0.f); acc[3] = fmaxf(acc[3] + b0.w, 0.f);
    acc[4] = fmaxf(acc[4] + b1.x, 0.f); acc[5] = fmaxf(acc[5] + b1.y, 0.f);
    acc[6] = fmaxf(acc[6] + b1.z, 0.f); acc[7] = fmaxf(acc[7] + b1.w, 0.f);

    uint4 hv, lv;
    split2(acc[0], acc[1], hv.x, lv.x);
    split2(acc[2], acc[3], hv.y, lv.y);
    split2(acc[4], acc[5], hv.z, lv.z);
    split2(acc[6], acc[7], hv.w, lv.w);
    size_t off = (size_t)row * F + loff;
    *reinterpret_cast<uint4*>(hi + off) = hv;
    *reinterpret_cast<uint4*>(lo + off) = lv;
}

// spmm2 fused: z = spmm(adj, HW2h) + b2; out1 = log_softmax(z); zhi/zlo = split(relu(z)).
// F=64: 8 threads/row; log-softmax via 8-lane subwarp shuffle reduce.
template<int F>
__global__ void spmm2_fused(const __half* __restrict__ src, const float* __restrict__ bias,
                            float* __restrict__ out1,
                            __nv_bfloat16* __restrict__ zhi, __nv_bfloat16* __restrict__ zlo,
                            int nrows) {
    constexpr int TPR = F / 8;              // 8
    constexpr int RPB = 256 / TPR;          // 32
    const int lane = threadIdx.x % TPR;
    const int row  = blockIdx.x * RPB + threadIdx.x / TPR;
    if (row >= nrows) return;

    const int s = g_rowptr[row];
    const int e = g_rowptr[row + 1];
    float acc[8];
    #pragma unroll
    for (int q = 0; q < 8; q++) acc[q] = 0.f;

    const size_t loff = (size_t)lane * 8;
    for (int j = s; j < e; j++) {
        int2  ev = g_edges[j];
        float v  = __int_as_float(ev.y);
        uint4 r = *reinterpret_cast<const uint4*>(src + (size_t)ev.x * F + loff);
        float2 f0 = __half22float2(*reinterpret_cast<__half2*>(&r.x));
        float2 f1 = __half22float2(*reinterpret_cast<__half2*>(&r.y));
        float2 f2 = __half22float2(*reinterpret_cast<__half2*>(&r.z));
        float2 f3 = __half22float2(*reinterpret_cast<__half2*>(&r.w));
        acc[0] = fmaf(v, f0.x, acc[0]); acc[1] = fmaf(v, f0.y, acc[1]);
        acc[2] = fmaf(v, f1.x, acc[2]); acc[3] = fmaf(v, f1.y, acc[3]);
        acc[4] = fmaf(v, f2.x, acc[4]); acc[5] = fmaf(v, f2.y, acc[5]);
        acc[6] = fmaf(v, f3.x, acc[6]); acc[7] = fmaf(v, f3.y, acc[7]);
    }
    float4 b0 = *reinterpret_cast<const float4*>(bias + loff);
    float4 b1 = *reinterpret_cast<const float4*>(bias + loff + 4);
    acc[0] += b0.x; acc[1] += b0.y; acc[2] += b0.z; acc[3] += b0.w;
    acc[4] += b1.x; acc[5] += b1.y; acc[6] += b1.z; acc[7] += b1.w;

    // split(relu(z)) for GEMM3
    size_t off = (size_t)row * F + loff;
    uint4 hv, lv;
    split2(fmaxf(acc[0], 0.f), fmaxf(acc[1], 0.f), hv.x, lv.x);
    split2(fmaxf(acc[2], 0.f), fmaxf(acc[3], 0.f), hv.y, lv.y);
    split2(fmaxf(acc[4], 0.f), fmaxf(acc[5], 0.f), hv.z, lv.z);
    split2(fmaxf(acc[6], 0.f), fmaxf(acc[7], 0.f), hv.w, lv.w);
    *reinterpret_cast<uint4*>(zhi + off) = hv;
    *reinterpret_cast<uint4*>(zlo + off) = lv;

    // log_softmax across the row (8 lanes x 8 values); M % 32 == 0 -> no divergence
    float m = acc[0];
    #pragma unroll
    for (int q = 1; q < 8; q++) m = fmaxf(m, acc[q]);
    #pragma unroll
    for (int o = 1; o < 8; o <<= 1) m = fmaxf(m, __shfl_xor_sync(0xffffffffu, m, o));
    float ssum = 0.f;
    #pragma unroll
    for (int q = 0; q < 8; q++) ssum += expf(acc[q] - m);
    #pragma unroll
    for (int o = 1; o < 8; o <<= 1) ssum += __shfl_xor_sync(0xffffffffu, ssum, o);
    float ls = m + logf(ssum);

    *reinterpret_cast<float4*>(out1 + off) =
        make_float4(acc[0] - ls, acc[1] - ls, acc[2] - ls, acc[3] - ls);
    *reinterpret_cast<float4*>(out1 + off + 4) =
        make_float4(acc[4] - ls, acc[5] - ls, acc[6] - ls, acc[7] - ls);
}

// ---------------- launch ------------------------------------------------------------
extern "C" void kernel_launch(void* const* d_in, const int* in_sizes, int n_in,
                              void* d_out, int out_size) {
    const float* x    = (const float*)d_in[0];
    const float* vals = (const float*)d_in[1];
    const float* W1   = (const float*)d_in[2];
    const float* b1   = (const float*)d_in[3];
    const float* W2   = (const float*)d_in[4];
    const float* b2   = (const float*)d_in[5];
    const float* W3   = (const float*)d_in[6];
    const float* b3   = (const float*)d_in[7];
    const int*   rows = (const int*)d_in[8];
    const int*   cols = (const int*)d_in[9];

    const int E = in_sizes[8];
    const int M = in_sizes[0] / F_IN;   // 100000

    float* out1 = (float*)d_out;                      // log_softmax [M, 64]
    float* out2 = (float*)d_out + (size_t)M * F_CLS;  // projection  [M, 128]

    __half *pXW1h, *pHW2h;
    __nv_bfloat16 *phhi, *phlo, *pzhi, *pzlo;
    __nv_bfloat16 *pw1thi, *pw1tlo, *pw2thi, *pw2tlo, *pw3thi, *pw3tlo;
    cudaGetSymbolAddress((void**)&pXW1h, g_XW1h);
    cudaGetSymbolAddress((void**)&pHW2h, g_HW2h);
    cudaGetSymbolAddress((void**)&phhi,  g_hhi);
    cudaGetSymbolAddress((void**)&phlo,  g_hlo);
    cudaGetSymbolAddress((void**)&pzhi,  g_zhi);
    cudaGetSymbolAddress((void**)&pzlo,  g_zlo);
    cudaGetSymbolAddress((void**)&pw1thi, g_w1thi);
    cudaGetSymbolAddress((void**)&pw1tlo, g_w1tlo);
    cudaGetSymbolAddress((void**)&pw2thi, g_w2thi);
    cudaGetSymbolAddress((void**)&pw2tlo, g_w2tlo);
    cudaGetSymbolAddress((void**)&pw3thi, g_w3thi);
    cudaGetSymbolAddress((void**)&pw3tlo, g_w3tlo);

    constexpr int SMEM1 = 3 * 65536;                // gemm1_fused: 196608
    constexpr int SMEM2 = 3 * (16384 + 64 * 128);   // gemm2: 73728
    constexpr int SMEM3 = 3 * (16384 + 128 * 128);  // gemm3: 98304
    cudaFuncSetAttribute(gemm1_fused, cudaFuncAttributeMaxDynamicSharedMemorySize, SMEM1);
    cudaFuncSetAttribute(gemm_mma<64, F_HID, F_CLS, __half>,
                         cudaFuncAttributeMaxDynamicSharedMemorySize, SMEM2);
    cudaFuncSetAttribute(gemm_mma<128, F_CLS, F_PROJ, float>,
                         cudaFuncAttributeMaxDynamicSharedMemorySize, SMEM3);

    const int MT = NN_PAD / 128;  // 782 row tiles

    // 1) bucket edges into CSR (reused by both spmms)
    k_zero_counts<<<(M + 255) / 256, 256>>>(M);
    k_hist<<<(E + 1023) / 1024, 256>>>(rows, E);
    k_scan<<<1, 1024>>>(M);
    k_scatter<<<(E + 1023) / 1024, 256>>>(rows, cols, vals, E);

    // 2) weight transpose+split (cheap)
    k_transpose_split<<<(F_IN * F_HID + 255) / 256, 256>>>(W1, pw1thi, pw1tlo, F_IN, F_HID);
    k_transpose_split<<<(F_HID * F_CLS + 255) / 256, 256>>>(W2, pw2thi, pw2tlo, F_HID, F_CLS);
    k_transpose_split<<<(F_CLS * F_PROJ + 255) / 256, 256>>>(W3, pw3thi, pw3tlo, F_CLS, F_PROJ);

    // 3) XW1 = x @ W1 (fused in-kernel split, full-N tile, fp16 out)
    gemm1_fused<<<MT, 512, SMEM1>>>(x, pw1thi, pw1tlo, pXW1h, M);

    // 4) h = relu(spmm(adj, XW1) + b1) -> bf16 hi/lo (fp16 gather)
    spmm1_fp16<F_HID><<<(M + 7) / 8, 256>>>(pXW1h, b1, phhi, phlo, M);

    // 5) HW2 = h @ W2 (tensor cores, fp16 out)
    gemm_mma<64, F_HID, F_CLS, __half><<<dim3(MT, 1), 256, SMEM2>>>(
        phhi, phlo, pw2thi, pw2tlo, nullptr, pHW2h, M);

    // 6) z = spmm + b2; out1 = log_softmax(z); relu(z) split for GEMM3 (all fused)
    spmm2_fused<F_CLS><<<(M + 31) / 32, 256>>>(pHW2h, b2, out1, pzhi, pzlo, M);

    // 7) out2 = relu(z) @ W3 + b3 (tensor cores, fp32 out + bias)
    gemm_mma<128, F_CLS, F_PROJ, float><<<dim3(MT, 1), 256, SMEM3>>>(
        pzhi, pzlo, pw3thi, pw3tlo, b3, out2, M);
}

// round 7
// speedup vs baseline: 2.5453x; 1.3292x over previous
#include <cuda_runtime.h>
#include <cuda_bf16.h>
#include <cuda_fp16.h>
#include <cstdint>

#define NN 100000
#define NN_PAD 100096      // 782 * 128
#define NE_MAX 3400000
#define F_IN   512
#define F_HID  256
#define F_CLS  64
#define F_PROJ 128

// ---------------- scratch (static device globals; no allocation) ----------------
__device__ __half g_XW1h[(size_t)NN * F_HID];   // x @ W1 (fp16)
__device__ __half g_HW2h[(size_t)NN * F_CLS];   // h @ W2 (fp16)
__device__ __nv_bfloat16 g_hhi[(size_t)NN_PAD * F_HID];
__device__ __nv_bfloat16 g_hlo[(size_t)NN_PAD * F_HID];
__device__ __nv_bfloat16 g_zhi[(size_t)NN_PAD * F_CLS];   // relu(z) split
__device__ __nv_bfloat16 g_zlo[(size_t)NN_PAD * F_CLS];
__device__ __nv_bfloat16 g_w1thi[F_HID * F_IN];   // W1^T [256,512]
__device__ __nv_bfloat16 g_w1tlo[F_HID * F_IN];
__device__ __nv_bfloat16 g_w2thi[F_CLS * F_HID];  // W2^T [64,256]
__device__ __nv_bfloat16 g_w2tlo[F_CLS * F_HID];
__device__ __nv_bfloat16 g_w3thi[F_PROJ * F_CLS]; // W3^T [128,64]
__device__ __nv_bfloat16 g_w3tlo[F_PROJ * F_CLS];
__device__ int   g_counts[NN];
__device__ int   g_rowptr[NN + 1];
__device__ int   g_cursor[NN];
__device__ int2  g_edges[NE_MAX];   // (col, val-as-int) packed

// ---------------- PTX helpers (sm_103-safe; no tcgen05) ---------------------------
__device__ __forceinline__ uint32_t smem_to_u32(const void* p) {
    uint32_t a;
    asm("{ .reg .u64 t; cvta.to.shared.u64 t, %1; cvt.u32.u64 %0, t; }" : "=r"(a) : "l"(p));
    return a;
}
#define CP_ASYNC16(dst, src) \
    asm volatile("cp.async.cg.shared.global [%0], [%1], 16;" :: "r"(dst), "l"(src))
#define CP_ASYNC16_Z(dst, src, sz) \
    asm volatile("cp.async.cg.shared.global [%0], [%1], 16, %2;" :: "r"(dst), "l"(src), "r"(sz))
#define CP_COMMIT() asm volatile("cp.async.commit_group;" ::: "memory")
#define CP_WAIT(N)  asm volatile("cp.async.wait_group %0;" :: "n"(N) : "memory")

#define LDSM_X4(r, addr) \
    asm volatile("ldmatrix.sync.aligned.m8n8.x4.shared.b16 {%0,%1,%2,%3}, [%4];" \
        : "=r"((r)[0]), "=r"((r)[1]), "=r"((r)[2]), "=r"((r)[3]) : "r"(addr))

__device__ __forceinline__ void mma16816(float* c, const uint32_t* a, uint32_t b0, uint32_t b1) {
    asm volatile("mma.sync.aligned.m16n8k16.row.col.f32.bf16.bf16.f32 "
        "{%0,%1,%2,%3}, {%4,%5,%6,%7}, {%8,%9}, {%0,%1,%2,%3};"
        : "+f"(c[0]), "+f"(c[1]), "+f"(c[2]), "+f"(c[3])
        : "r"(a[0]), "r"(a[1]), "r"(a[2]), "r"(a[3]), "r"(b0), "r"(b1));
}

// XOR swizzle for 64B-row tiles: row r, 16B-column c16 (0..3)
__device__ __forceinline__ uint32_t swz(int r, int c16) {
    return (uint32_t)(r * 64 + ((c16 ^ ((r >> 1) & 3)) << 4));
}

// pack 2 floats -> hi bf16x2 + lo bf16x2 (residual)
__device__ __forceinline__ void split2(float a, float b, uint32_t& hi, uint32_t& lo) {
    __nv_bfloat16 ha = __float2bfloat16(a), hb = __float2bfloat16(b);
    __nv_bfloat16 la = __float2bfloat16(a - __bfloat162float(ha));
    __nv_bfloat16 lb = __float2bfloat16(b - __bfloat162float(hb));
    __nv_bfloat162 h; h.x = ha; h.y = hb;
    __nv_bfloat162 l; l.x = la; l.y = lb;
    hi = *(uint32_t*)&h;
    lo = *(uint32_t*)&l;
}

// epilogue store helpers (fp32 or fp16 output)
__device__ __forceinline__ void store2(float* p, float x, float y) {
    *reinterpret_cast<float2*>(p) = make_float2(x, y);
}
__device__ __forceinline__ void store2(__half* p, float x, float y) {
    *reinterpret_cast<__half2*>(p) = __floats2half2_rn(x, y);
}

// ---------------- edge bucketing --------------------------------------------------
__global__ void k_zero_counts(int n) {
    int i = blockIdx.x * blockDim.x + threadIdx.x;
    if (i < n) g_counts[i] = 0;
}
__global__ void k_hist(const int* __restrict__ rows, int E) {
    int base = (blockIdx.x * blockDim.x + threadIdx.x) * 4;
    #pragma unroll
    for (int q = 0; q < 4; q++) {
        int e = base + q;
        if (e < E) atomicAdd(&g_counts[rows[e]], 1);
    }
}
__global__ void k_scan(int n) {
    __shared__ int part[1024];
    int tid = threadIdx.x;
    int per = (n + 1023) >> 10;
    int st = tid * per;
    int en = st + per; if (en > n) en = n;
    int s = 0;
    for (int i = st; i < en; i++) s += g_counts[i];
    part[tid] = s;
    __syncthreads();
    #pragma unroll
    for (int off = 1; off < 1024; off <<= 1) {
        int v = (tid >= off) ? part[tid - off] : 0;
        __syncthreads();
        part[tid] += v;
        __syncthreads();
    }
    int base = (tid == 0) ? 0 : part[tid - 1];
    for (int i = st; i < en; i++) {
        int c = g_counts[i];
        g_rowptr[i] = base;
        g_cursor[i] = base;
        base += c;
    }
    if (tid == 1023) g_rowptr[n] = part[1023];
}
__global__ void k_scatter(const int* __restrict__ rows, const int* __restrict__ cols,
                          const float* __restrict__ vals, int E) {
    int base = (blockIdx.x * blockDim.x + threadIdx.x) * 4;
    #pragma unroll
    for (int q = 0; q < 4; q++) {
        int e = base + q;
        if (e < E) {
            int r = rows[e];
            int p = atomicAdd(&g_cursor[r], 1);
            g_edges[p] = make_int2(cols[e], __float_as_int(vals[e]));
        }
    }
}

// ---------------- transpose + split: W[K,N] -> T[N,K] bf16 hi/lo ------------------
__global__ void k_transpose_split(const float* __restrict__ W, __nv_bfloat16* __restrict__ Thi,
                                  __nv_bfloat16* __restrict__ Tlo, int K, int N) {
    int i = blockIdx.x * blockDim.x + threadIdx.x;
    if (i >= K * N) return;
    int k = i / N, n = i % N;
    float v = W[i];
    __nv_bfloat16 h = __float2bfloat16(v);
    __nv_bfloat16 l = __float2bfloat16(v - __bfloat162float(h));
    Thi[(size_t)n * K + k] = h;
    Tlo[(size_t)n * K + k] = l;
}

// ---------------- GEMM1: XW1h[M,256] = x[M,512] @ W1, fused fp32->hi/lo split ------
// 512 threads, 16 warps (4m x 4n), warp tile 32x64 (4 B groups). BK=32.
__global__ void __launch_bounds__(512, 1) gemm1_fused(
    const float* __restrict__ X,
    const __nv_bfloat16* __restrict__ Bhi, const __nv_bfloat16* __restrict__ Blo,
    __half* __restrict__ C, int Mrows)
{
    constexpr int K_TOT = 512, N_TOT = 256, NC = 16;
    constexpr int SS = 65536;
    constexpr int OFF_X = 0, OFF_AH = 16384, OFF_AL = 24576, OFF_BH = 32768;

    extern __shared__ __align__(128) char smem[];
    const uint32_t sb = smem_to_u32(smem);
    const int tid = threadIdx.x;
    const int wid = tid >> 5, lane = tid & 31;
    const int warpM = wid & 3, warpN = wid >> 2;
    const int m0 = blockIdx.x * 128;
    const int wm0 = warpM * 32, wn0 = warpN * 64;

    float acc[2][8][4];
    #pragma unroll
    for (int i = 0; i < 2; i++)
        #pragma unroll
        for (int j = 0; j < 8; j++)
            #pragma unroll
            for (int q = 0; q < 4; q++) acc[i][j][q] = 0.f;

    auto load_chunk = [&](int kc) {
        const uint32_t sd = sb + (uint32_t)(kc % 3) * SS;
        #pragma unroll
        for (int i = tid; i < 1024; i += 512) {
            int r = i >> 3, c = i & 7;
            uint32_t dst = sd + OFF_X + (uint32_t)i * 16;
            int rr = m0 + r;
            uint32_t sz = (rr < Mrows) ? 16u : 0u;
            if (rr >= Mrows) rr = m0;
            const char* g = (const char*)(X + (size_t)rr * K_TOT + kc * 32) + c * 16;
            CP_ASYNC16_Z(dst, g, sz);
        }
        #pragma unroll
        for (int i = tid; i < 2048; i += 512) {
            int buf = i >> 10, idx = i & 1023;
            int r = idx >> 2, c16 = idx & 3;
            uint32_t dst = sd + OFF_BH + (uint32_t)buf * 16384 + swz(r, c16);
            const char* g = (const char*)((buf ? Blo : Bhi) + (size_t)r * K_TOT + kc * 32)
                            + c16 * 16;
            CP_ASYNC16(dst, g);
        }
        CP_COMMIT();
    };

    load_chunk(0);
    load_chunk(1);

    for (int kc = 0; kc < NC; kc++) {
        if (kc + 1 < NC) { CP_WAIT(1); } else { CP_WAIT(0); }
        __syncthreads();

        char* basep = smem + (size_t)(kc % 3) * SS;
        {
            int r = tid >> 2, c16 = tid & 3;
            float4 f0 = *reinterpret_cast<const float4*>(basep + OFF_X + (size_t)tid * 32);
            float4 f1 = *reinterpret_cast<const float4*>(basep + OFF_X + (size_t)tid * 32 + 16);
            uint4 hv, lv;
            split2(f0.x, f0.y, hv.x, lv.x);
            split2(f0.z, f0.w, hv.y, lv.y);
            split2(f1.x, f1.y, hv.z, lv.z);
            split2(f1.z, f1.w, hv.w, lv.w);
            *reinterpret_cast<uint4*>(basep + OFF_AH + swz(r, c16)) = hv;
            *reinterpret_cast<uint4*>(basep + OFF_AL + swz(r, c16)) = lv;
        }
        __syncthreads();

        if (kc + 2 < NC) load_chunk(kc + 2);

        const uint32_t sA_hi = sb + (uint32_t)(kc % 3) * SS + OFF_AH;
        const uint32_t sA_lo = sA_hi + 8192;
        const uint32_t sB_hi = sb + (uint32_t)(kc % 3) * SS + OFF_BH;
        const uint32_t sB_lo = sB_hi + 16384;

        #pragma unroll
        for (int ks = 0; ks < 2; ks++) {
            uint32_t ahi[2][4], alo[2][4];
            #pragma unroll
            for (int mt = 0; mt < 2; mt++) {
                int row = wm0 + mt * 16 + (lane & 15);
                int c16 = ks * 2 + (lane >> 4);
                LDSM_X4(ahi[mt], sA_hi + swz(row, c16));
                LDSM_X4(alo[mt], sA_lo + swz(row, c16));
            }
            #pragma unroll
            for (int g = 0; g < 4; g++) {
                uint32_t bhi[4], blo[4];
                int row = wn0 + g * 16 + (lane & 15);
                int c16 = ks * 2 + (lane >> 4);
                LDSM_X4(bhi, sB_hi + swz(row, c16));
                LDSM_X4(blo, sB_lo + swz(row, c16));
                #pragma unroll
                for (int mt = 0; mt < 2; mt++)
                    #pragma unroll
                    for (int h = 0; h < 2; h++) {
                        int nt = g * 2 + h;
                        mma16816(acc[mt][nt], ahi[mt], bhi[h], bhi[2 + h]);
                        mma16816(acc[mt][nt], alo[mt], bhi[h], bhi[2 + h]);
                        mma16816(acc[mt][nt], ahi[mt], blo[h], blo[2 + h]);
                    }
            }
        }
        __syncthreads();
    }

    #pragma unroll
    for (int mt = 0; mt < 2; mt++) {
        int m = m0 + wm0 + mt * 16 + (lane >> 2);
        #pragma unroll
        for (int nt = 0; nt < 8; nt++) {
            int n = wn0 + nt * 8 + (lane & 3) * 2;
            if (m < Mrows)
                store2(C + (size_t)m * N_TOT + n, acc[mt][nt][0], acc[mt][nt][1]);
            if (m + 8 < Mrows)
                store2(C + (size_t)(m + 8) * N_TOT + n, acc[mt][nt][2], acc[mt][nt][3]);
        }
    }
}

// ---------------- split-bf16 GEMM via mma.sync (pre-split A), optional bias --------
template<int BN, int K_TOT, int N_TOT, typename TOUT>
__global__ void __launch_bounds__(256, 1) gemm_mma(
    const __nv_bfloat16* __restrict__ Ahi, const __nv_bfloat16* __restrict__ Alo,
    const __nv_bfloat16* __restrict__ Bhi, const __nv_bfloat16* __restrict__ Blo,
    const float* __restrict__ bias,
    TOUT* __restrict__ C, int Mrows)
{
    constexpr int NC = K_TOT / 32;
    constexpr int SS = 16384 + BN * 128;
    constexpr int NT16 = BN / 32;
    constexpr int NT8  = BN / 16;

    extern __shared__ __align__(128) char smem[];
    const uint32_t sb = smem_to_u32(smem);
    const int tid = threadIdx.x;
    const int wid = tid >> 5, lane = tid & 31;
    const int warpM = wid & 3, warpN = wid >> 2;
    const int m0 = blockIdx.x * 128;
    const int n_off = blockIdx.y * BN;
    const int wm0 = warpM * 32;
    const int wn0 = warpN * (BN / 2);

    float acc[2][NT8][4];
    #pragma unroll
    for (int i = 0; i < 2; i++)
        #pragma unroll
        for (int j = 0; j < NT8; j++)
            #pragma unroll
            for (int q = 0; q < 4; q++) acc[i][j][q] = 0.f;

    auto load_chunk = [&](int kc) {
        const uint32_t sd = sb + (uint32_t)(kc % 3) * SS;
        #pragma unroll
        for (int i = tid; i < 1024; i += 256) {
            int buf = i >> 9, idx = i & 511;
            int r = idx >> 2, c16 = idx & 3;
            uint32_t dst = sd + (uint32_t)buf * 8192 + swz(r, c16);
            const char* g = (const char*)((buf ? Alo : Ahi) + (size_t)(m0 + r) * K_TOT)
                            + kc * 64 + c16 * 16;
            CP_ASYNC16(dst, g);
        }
        #pragma unroll
        for (int i = tid; i < 2 * BN * 4; i += 256) {
            int buf = (i >= BN * 4);
            int idx = buf ? i - BN * 4 : i;
            int r = idx >> 2, c16 = idx & 3;
            uint32_t dst = sd + 16384 + (uint32_t)buf * (BN * 64) + swz(r, c16);
            const char* g = (const char*)((buf ? Blo : Bhi) + (size_t)(n_off + r) * K_TOT)
                            + kc * 64 + c16 * 16;
            CP_ASYNC16(dst, g);
        }
        CP_COMMIT();
    };

    load_chunk(0);
    if (NC > 1) load_chunk(1);

    for (int kc = 0; kc < NC; kc++) {
        if (kc + 1 < NC) { CP_WAIT(1); } else { CP_WAIT(0); }
        __syncthreads();
        if (kc + 2 < NC) load_chunk(kc + 2);

        const uint32_t sA_hi = sb + (uint32_t)(kc % 3) * SS;
        const uint32_t sA_lo = sA_hi + 8192;
        const uint32_t sB_hi = sA_lo + 8192;
        const uint32_t sB_lo = sB_hi + BN * 64;

        #pragma unroll
        for (int ks = 0; ks < 2; ks++) {
            uint32_t ahi[2][4], alo[2][4];
            #pragma unroll
            for (int mt = 0; mt < 2; mt++) {
                int row = wm0 + mt * 16 + (lane & 15);
                int c16 = ks * 2 + (lane >> 4);
                LDSM_X4(ahi[mt], sA_hi + swz(row, c16));
                LDSM_X4(alo[mt], sA_lo + swz(row, c16));
            }
            #pragma unroll
            for (int g = 0; g < NT16; g++) {
                uint32_t bhi[4], blo[4];
                int row = wn0 + g * 16 + (lane & 15);
                int c16 = ks * 2 + (lane >> 4);
                LDSM_X4(bhi, sB_hi + swz(row, c16));
                LDSM_X4(blo, sB_lo + swz(row, c16));
                #pragma unroll
                for (int mt = 0; mt < 2; mt++)
                    #pragma unroll
                    for (int h = 0; h < 2; h++) {
                        int nt = g * 2 + h;
                        mma16816(acc[mt][nt], ahi[mt], bhi[h], bhi[2 + h]);
                        mma16816(acc[mt][nt], alo[mt], bhi[h], bhi[2 + h]);
                        mma16816(acc[mt][nt], ahi[mt], blo[h], blo[2 + h]);
                    }
            }
        }
        __syncthreads();
    }

    #pragma unroll
    for (int mt = 0; mt < 2; mt++) {
        int m = m0 + wm0 + mt * 16 + (lane >> 2);
        #pragma unroll
        for (int nt = 0; nt < NT8; nt++) {
            int n = n_off + wn0 + nt * 8 + (lane & 3) * 2;
            float bx = 0.f, by = 0.f;
            if (bias) {
                float2 bv = *reinterpret_cast<const float2*>(bias + n);
                bx = bv.x; by = bv.y;
            }
            if (m < Mrows)
                store2(C + (size_t)m * N_TOT + n, acc[mt][nt][0] + bx, acc[mt][nt][1] + by);
            if (m + 8 < Mrows)
                store2(C + (size_t)(m + 8) * N_TOT + n, acc[mt][nt][2] + bx, acc[mt][nt][3] + by);
        }
    }
}

// ---------------- SpMM over sorted CSR, fp16 gather -------------------------------
template<int F>
__global__ void spmm1_fp16(const __half* __restrict__ src, const float* __restrict__ bias,
                           __nv_bfloat16* __restrict__ hi, __nv_bfloat16* __restrict__ lo,
                           int nrows) {
    constexpr int TPR = F / 8;
    constexpr int RPB = 256 / TPR;
    const int lane = threadIdx.x % TPR;
    const int row  = blockIdx.x * RPB + threadIdx.x / TPR;
    if (row >= nrows) return;

    const int s = g_rowptr[row];
    const int e = g_rowptr[row + 1];
    float acc[8];
    #pragma unroll
    for (int q = 0; q < 8; q++) acc[q] = 0.f;

    const size_t loff = (size_t)lane * 8;
    for (int j = s; j < e; j++) {
        int2  ev = g_edges[j];
        float v  = __int_as_float(ev.y);
        uint4 r = *reinterpret_cast<const uint4*>(src + (size_t)ev.x * F + loff);
        float2 f0 = __half22float2(*reinterpret_cast<__half2*>(&r.x));
        float2 f1 = __half22float2(*reinterpret_cast<__half2*>(&r.y));
        float2 f2 = __half22float2(*reinterpret_cast<__half2*>(&r.z));
        float2 f3 = __half22float2(*reinterpret_cast<__half2*>(&r.w));
        acc[0] = fmaf(v, f0.x, acc[0]); acc[1] = fmaf(v, f0.y, acc[1]);
        acc[2] = fmaf(v, f1.x, acc[2]); acc[3] = fmaf(v, f1.y, acc[3]);
        acc[4] = fmaf(v, f2.x, acc[4]); acc[5] = fmaf(v, f2.y, acc[5]);
        acc[6] = fmaf(v, f3.x, acc[6]); acc[7] = fmaf(v, f3.y, acc[7]);
    }
    float4 b0 = *reinterpret_cast<const float4*>(bias + loff);
    float4 b1 = *reinterpret_cast<const float4*>(bias + loff + 4);
    acc[0] = fmaxf(acc[0] + b0.x, 0.f); acc[1] = fmaxf(acc[1] + b0.y, 0.f);
    acc[2] = fmaxf(acc[2] + b0.z, 0.f); acc[3] = fmaxf(acc[3] + b0.w, 0.f);
    acc[4] = fmaxf(acc[4] + b1.x, 0.f); acc[5] = fmaxf(acc[5] + b1.y, 0.f);
    acc[6] = fmaxf(acc[6] + b1.z, 0.f); acc[7] = fmaxf(acc[7] + b1.w, 0.f);

    uint4 hv, lv;
    split2(acc[0], acc[1], hv.x, lv.x);
    split2(acc[2], acc[3], hv.y, lv.y);
    split2(acc[4], acc[5], hv.z, lv.z);
    split2(acc[6], acc[7], hv.w, lv.w);
    size_t off = (size_t)row * F + loff;
    *reinterpret_cast<uint4*>(hi + off) = hv;
    *reinterpret_cast<uint4*>(lo + off) = lv;
}

// spmm2 fused: z = spmm + b2; out1 = log_softmax(z); zhi/zlo = split(relu(z)).
template<int F>
__global__ void spmm2_fused(const __half* __restrict__ src, const float* __restrict__ bias,
                            float* __restrict__ out1,
                            __nv_bfloat16* __restrict__ zhi, __nv_bfloat16* __restrict__ zlo,
                            int nrows) {
    constexpr int TPR = F / 8;              // 8
    constexpr int RPB = 256 / TPR;          // 32
    const int lane = threadIdx.x % TPR;
    const int row  = blockIdx.x * RPB + threadIdx.x / TPR;
    if (row >= nrows) return;

    const int s = g_rowptr[row];
    const int e = g_rowptr[row + 1];
    float acc[8];
    #pragma unroll
    for (int q = 0; q < 8; q++) acc[q] = 0.f;

    const size_t loff = (size_t)lane * 8;
    for (int j = s; j < e; j++) {
        int2  ev = g_edges[j];
        float v  = __int_as_float(ev.y);
        uint4 r = *reinterpret_cast<const uint4*>(src + (size_t)ev.x * F + loff);
        float2 f0 = __half22float2(*reinterpret_cast<__half2*>(&r.x));
        float2 f1 = __half22float2(*reinterpret_cast<__half2*>(&r.y));
        float2 f2 = __half22float2(*reinterpret_cast<__half2*>(&r.z));
        float2 f3 = __half22float2(*reinterpret_cast<__half2*>(&r.w));
        acc[0] = fmaf(v, f0.x, acc[0]); acc[1] = fmaf(v, f0.y, acc[1]);
        acc[2] = fmaf(v, f1.x, acc[2]); acc[3] = fmaf(v, f1.y, acc[3]);
        acc[4] = fmaf(v, f2.x, acc[4]); acc[5] = fmaf(v, f2.y, acc[5]);
        acc[6] = fmaf(v, f3.x, acc[6]); acc[7] = fmaf(v, f3.y, acc[7]);
    }
    float4 b0 = *reinterpret_cast<const float4*>(bias + loff);
    float4 b1 = *reinterpret_cast<const float4*>(bias + loff + 4);
    acc[0] += b0.x; acc[1] += b0.y; acc[2] += b0.z; acc[3] += b0.w;
    acc[4] += b1.x; acc[5] += b1.y; acc[6] += b1.z; acc[7] += b1.w;

    size_t off = (size_t)row * F + loff;
    uint4 hv, lv;
    split2(fmaxf(acc[0], 0.f), fmaxf(acc[1], 0.f), hv.x, lv.x);
    split2(fmaxf(acc[2], 0.f), fmaxf(acc[3], 0.f), hv.y, lv.y);
    split2(fmaxf(acc[4], 0.f), fmaxf(acc[5], 0.f), hv.z, lv.z);
    split2(fmaxf(acc[6], 0.f), fmaxf(acc[7], 0.f), hv.w, lv.w);
    *reinterpret_cast<uint4*>(zhi + off) = hv;
    *reinterpret_cast<uint4*>(zlo + off) = lv;

    float m = acc[0];
    #pragma unroll
    for (int q = 1; q < 8; q++) m = fmaxf(m, acc[q]);
    #pragma unroll
    for (int o = 1; o < 8; o <<= 1) m = fmaxf(m, __shfl_xor_sync(0xffffffffu, m, o));
    float ssum = 0.f;
    #pragma unroll
    for (int q = 0; q < 8; q++) ssum += expf(acc[q] - m);
    #pragma unroll
    for (int o = 1; o < 8; o <<= 1) ssum += __shfl_xor_sync(0xffffffffu, ssum, o);
    float ls = m + logf(ssum);

    *reinterpret_cast<float4*>(out1 + off) =
        make_float4(acc[0] - ls, acc[1] - ls, acc[2] - ls, acc[3] - ls);
    *reinterpret_cast<float4*>(out1 + off + 4) =
        make_float4(acc[4] - ls, acc[5] - ls, acc[6] - ls, acc[7] - ls);
}

// ---------------- launch ------------------------------------------------------------
// Side stream + events for the forked capture branch (created lazily on the
// un-captured correctness call; reused identically on every call so the recorded
// work/DAG is deterministic).
static cudaStream_t s_side = nullptr;
static cudaEvent_t  s_evFork = nullptr, s_evJoin = nullptr;

extern "C" void kernel_launch(void* const* d_in, const int* in_sizes, int n_in,
                              void* d_out, int out_size) {
    const float* x    = (const float*)d_in[0];
    const float* vals = (const float*)d_in[1];
    const float* W1   = (const float*)d_in[2];
    const float* b1   = (const float*)d_in[3];
    const float* W2   = (const float*)d_in[4];
    const float* b2   = (const float*)d_in[5];
    const float* W3   = (const float*)d_in[6];
    const float* b3   = (const float*)d_in[7];
    const int*   rows = (const int*)d_in[8];
    const int*   cols = (const int*)d_in[9];

    const int E = in_sizes[8];
    const int M = in_sizes[0] / F_IN;   // 100000

    float* out1 = (float*)d_out;                      // log_softmax [M, 64]
    float* out2 = (float*)d_out + (size_t)M * F_CLS;  // projection  [M, 128]

    __half *pXW1h, *pHW2h;
    __nv_bfloat16 *phhi, *phlo, *pzhi, *pzlo;
    __nv_bfloat16 *pw1thi, *pw1tlo, *pw2thi, *pw2tlo, *pw3thi, *pw3tlo;
    cudaGetSymbolAddress((void**)&pXW1h, g_XW1h);
    cudaGetSymbolAddress((void**)&pHW2h, g_HW2h);
    cudaGetSymbolAddress((void**)&phhi,  g_hhi);
    cudaGetSymbolAddress((void**)&phlo,  g_hlo);
    cudaGetSymbolAddress((void**)&pzhi,  g_zhi);
    cudaGetSymbolAddress((void**)&pzlo,  g_zlo);
    cudaGetSymbolAddress((void**)&pw1thi, g_w1thi);
    cudaGetSymbolAddress((void**)&pw1tlo, g_w1tlo);
    cudaGetSymbolAddress((void**)&pw2thi, g_w2thi);
    cudaGetSymbolAddress((void**)&pw2tlo, g_w2tlo);
    cudaGetSymbolAddress((void**)&pw3thi, g_w3thi);
    cudaGetSymbolAddress((void**)&pw3tlo, g_w3tlo);

    if (s_side == nullptr) {
        cudaStreamCreateWithFlags(&s_side, cudaStreamNonBlocking);
        cudaEventCreateWithFlags(&s_evFork, cudaEventDisableTiming);
        cudaEventCreateWithFlags(&s_evJoin, cudaEventDisableTiming);
    }

    constexpr int SMEM1 = 3 * 65536;                // gemm1_fused: 196608
    constexpr int SMEM2 = 3 * (16384 + 64 * 128);   // gemm2: 73728
    constexpr int SMEM3 = 3 * (16384 + 128 * 128);  // gemm3: 98304
    cudaFuncSetAttribute(gemm1_fused, cudaFuncAttributeMaxDynamicSharedMemorySize, SMEM1);
    cudaFuncSetAttribute(gemm_mma<64, F_HID, F_CLS, __half>,
                         cudaFuncAttributeMaxDynamicSharedMemorySize, SMEM2);
    cudaFuncSetAttribute(gemm_mma<128, F_CLS, F_PROJ, float>,
                         cudaFuncAttributeMaxDynamicSharedMemorySize, SMEM3);

    const int MT = NN_PAD / 128;  // 782 row tiles

    // ---- fork: CSR build on side stream, concurrent with GEMM1 path --------------
    cudaEventRecord(s_evFork, 0);
    cudaStreamWaitEvent(s_side, s_evFork, 0);

    k_zero_counts<<<(M + 255) / 256, 256, 0, s_side>>>(M);
    k_hist<<<(E + 1023) / 1024, 256, 0, s_side>>>(rows, E);
    k_scan<<<1, 1024, 0, s_side>>>(M);
    k_scatter<<<(E + 1023) / 1024, 256, 0, s_side>>>(rows, cols, vals, E);
    cudaEventRecord(s_evJoin, s_side);

    // ---- main stream: weight prep + GEMM1 ----------------------------------------
    k_transpose_split<<<(F_IN * F_HID + 255) / 256, 256>>>(W1, pw1thi, pw1tlo, F_IN, F_HID);
    k_transpose_split<<<(F_HID * F_CLS + 255) / 256, 256>>>(W2, pw2thi, pw2tlo, F_HID, F_CLS);
    k_transpose_split<<<(F_CLS * F_PROJ + 255) / 256, 256>>>(W3, pw3thi, pw3tlo, F_CLS, F_PROJ);

    gemm1_fused<<<MT, 512, SMEM1>>>(x, pw1thi, pw1tlo, pXW1h, M);

    // ---- join: SpMM1 needs both CSR and XW1 ---------------------------------------
    cudaStreamWaitEvent(0, s_evJoin, 0);

    spmm1_fp16<F_HID><<<(M + 7) / 8, 256>>>(pXW1h, b1, phhi, phlo, M);

    gemm_mma<64, F_HID, F_CLS, __half><<<dim3(MT, 1), 256, SMEM2>>>(
        phhi, phlo, pw2thi, pw2tlo, nullptr, pHW2h, M);

    spmm2_fused<F_CLS><<<(M + 31) / 32, 256>>>(pHW2h, b2, out1, pzhi, pzlo, M);

    gemm_mma<128, F_CLS, F_PROJ, float><<<dim3(MT, 1), 256, SMEM3>>>(
        pzhi, pzlo, pw3thi, pw3tlo, b3, out2, M);
}

// round 8
// speedup vs baseline: 3.0566x; 1.2009x over previous
#include <cuda_runtime.h>
#include <cuda_fp16.h>
#include <cstdint>

#define NN 100000
#define NN_PAD 100096      // 782 * 128
#define NE_MAX 3400000
#define F_IN   512
#define F_HID  256
#define F_CLS  64
#define F_PROJ 128

// ---------------- scratch (static device globals; no allocation) ----------------
__device__ __half g_XW1h[(size_t)NN_PAD * F_HID];  // x @ W1 (fp16)
__device__ __half g_h   [(size_t)NN_PAD * F_HID];  // relu(spmm+b1) (fp16)
__device__ __half g_HW2h[(size_t)NN_PAD * F_CLS];  // h @ W2 (fp16)
__device__ float  g_z   [(size_t)NN * F_CLS];      // spmm + b2 (fp32)
__device__ __half g_zh  [(size_t)NN_PAD * F_CLS];  // relu(z) (fp16)
__device__ __half g_w1t[F_HID * F_IN];    // W1^T [256,512]
__device__ __half g_w2t[F_CLS * F_HID];   // W2^T [64,256]
__device__ __half g_w3t[F_PROJ * F_CLS];  // W3^T [128,64]
__device__ int   g_counts[NN];
__device__ int   g_rowptr[NN + 1];
__device__ int   g_cursor[NN];
__device__ int2  g_edges[NE_MAX];   // (col, val-as-int) packed

// ---------------- PTX helpers (sm_103-safe; no tcgen05) ---------------------------
__device__ __forceinline__ uint32_t smem_to_u32(const void* p) {
    uint32_t a;
    asm("{ .reg .u64 t; cvta.to.shared.u64 t, %1; cvt.u32.u64 %0, t; }" : "=r"(a) : "l"(p));
    return a;
}
#define CP_ASYNC16(dst, src) \
    asm volatile("cp.async.cg.shared.global [%0], [%1], 16;" :: "r"(dst), "l"(src))
#define CP_ASYNC16_Z(dst, src, sz) \
    asm volatile("cp.async.cg.shared.global [%0], [%1], 16, %2;" :: "r"(dst), "l"(src), "r"(sz))
#define CP_COMMIT() asm volatile("cp.async.commit_group;" ::: "memory")
#define CP_WAIT(N)  asm volatile("cp.async.wait_group %0;" :: "n"(N) : "memory")

#define LDSM_X4(r, addr) \
    asm volatile("ldmatrix.sync.aligned.m8n8.x4.shared.b16 {%0,%1,%2,%3}, [%4];" \
        : "=r"((r)[0]), "=r"((r)[1]), "=r"((r)[2]), "=r"((r)[3]) : "r"(addr))

__device__ __forceinline__ void mma16816h(float* c, const uint32_t* a, uint32_t b0, uint32_t b1) {
    asm volatile("mma.sync.aligned.m16n8k16.row.col.f32.f16.f16.f32 "
        "{%0,%1,%2,%3}, {%4,%5,%6,%7}, {%8,%9}, {%0,%1,%2,%3};"
        : "+f"(c[0]), "+f"(c[1]), "+f"(c[2]), "+f"(c[3])
        : "r"(a[0]), "r"(a[1]), "r"(a[2]), "r"(a[3]), "r"(b0), "r"(b1));
}

// XOR swizzle for 64B-row tiles: row r, 16B-column c16 (0..3)
__device__ __forceinline__ uint32_t swz(int r, int c16) {
    return (uint32_t)(r * 64 + ((c16 ^ ((r >> 1) & 3)) << 4));
}

// epilogue store helpers (fp32 or fp16 output)
__device__ __forceinline__ void store2(float* p, float x, float y) {
    *reinterpret_cast<float2*>(p) = make_float2(x, y);
}
__device__ __forceinline__ void store2(__half* p, float x, float y) {
    *reinterpret_cast<__half2*>(p) = __floats2half2_rn(x, y);
}

// ---------------- edge bucketing --------------------------------------------------
__global__ void k_zero_counts(int n) {
    int i = blockIdx.x * blockDim.x + threadIdx.x;
    if (i < n) g_counts[i] = 0;
}
__global__ void k_hist(const int* __restrict__ rows, int E) {
    int base = (blockIdx.x * blockDim.x + threadIdx.x) * 4;
    #pragma unroll
    for (int q = 0; q < 4; q++) {
        int e = base + q;
        if (e < E) atomicAdd(&g_counts[rows[e]], 1);
    }
}
__global__ void k_scan(int n) {
    __shared__ int part[1024];
    int tid = threadIdx.x;
    int per = (n + 1023) >> 10;
    int st = tid * per;
    int en = st + per; if (en > n) en = n;
    int s = 0;
    for (int i = st; i < en; i++) s += g_counts[i];
    part[tid] = s;
    __syncthreads();
    #pragma unroll
    for (int off = 1; off < 1024; off <<= 1) {
        int v = (tid >= off) ? part[tid - off] : 0;
        __syncthreads();
        part[tid] += v;
        __syncthreads();
    }
    int base = (tid == 0) ? 0 : part[tid - 1];
    for (int i = st; i < en; i++) {
        int c = g_counts[i];
        g_rowptr[i] = base;
        g_cursor[i] = base;
        base += c;
    }
    if (tid == 1023) g_rowptr[n] = part[1023];
}
__global__ void k_scatter(const int* __restrict__ rows, const int* __restrict__ cols,
                          const float* __restrict__ vals, int E) {
    int base = (blockIdx.x * blockDim.x + threadIdx.x) * 4;
    #pragma unroll
    for (int q = 0; q < 4; q++) {
        int e = base + q;
        if (e < E) {
            int r = rows[e];
            int p = atomicAdd(&g_cursor[r], 1);
            g_edges[p] = make_int2(cols[e], __float_as_int(vals[e]));
        }
    }
}

// ---------------- transpose: W[K,N] -> T[N,K] fp16 --------------------------------
__global__ void k_transpose_h(const float* __restrict__ W, __half* __restrict__ T,
                              int K, int N) {
    int i = blockIdx.x * blockDim.x + threadIdx.x;
    if (i >= K * N) return;
    int k = i / N, n = i % N;
    T[(size_t)n * K + k] = __float2half(W[i]);
}

// ---------------- GEMM1: XW1h[M,256] = x[M,512] @ W1, fused fp32->fp16 convert -----
// 512 threads, 16 warps (4m x 4n), warp tile 32x64. BK=32, 3-stage cp.async.
__global__ void __launch_bounds__(512, 1) gemm1_fused(
    const float* __restrict__ X, const __half* __restrict__ B,
    __half* __restrict__ C, int Mrows)
{
    constexpr int K_TOT = 512, N_TOT = 256, NC = 16;
    constexpr int SS = 40960;                 // x 16K + A 8K + B 16K
    constexpr int OFF_X = 0, OFF_A = 16384, OFF_B = 24576;

    extern __shared__ __align__(128) char smem[];
    const uint32_t sb = smem_to_u32(smem);
    const int tid = threadIdx.x;
    const int wid = tid >> 5, lane = tid & 31;
    const int warpM = wid & 3, warpN = wid >> 2;
    const int m0 = blockIdx.x * 128;
    const int wm0 = warpM * 32, wn0 = warpN * 64;

    float acc[2][8][4];
    #pragma unroll
    for (int i = 0; i < 2; i++)
        #pragma unroll
        for (int j = 0; j < 8; j++)
            #pragma unroll
            for (int q = 0; q < 4; q++) acc[i][j][q] = 0.f;

    auto load_chunk = [&](int kc) {
        const uint32_t sd = sb + (uint32_t)(kc % 3) * SS;
        // x fp32: 128 rows x 128B -> 1024 16B units, linear
        #pragma unroll
        for (int i = tid; i < 1024; i += 512) {
            int r = i >> 3, c = i & 7;
            uint32_t dst = sd + OFF_X + (uint32_t)i * 16;
            int rr = m0 + r;
            uint32_t sz = (rr < Mrows) ? 16u : 0u;
            if (rr >= Mrows) rr = m0;
            const char* g = (const char*)(X + (size_t)rr * K_TOT + kc * 32) + c * 16;
            CP_ASYNC16_Z(dst, g, sz);
        }
        // B fp16: 256 rows x 4 16B units, swizzled
        #pragma unroll
        for (int i = tid; i < 1024; i += 512) {
            int r = i >> 2, c16 = i & 3;
            uint32_t dst = sd + OFF_B + swz(r, c16);
            const char* g = (const char*)(B + (size_t)r * K_TOT + kc * 32) + c16 * 16;
            CP_ASYNC16(dst, g);
        }
        CP_COMMIT();
    };

    load_chunk(0);
    load_chunk(1);

    for (int kc = 0; kc < NC; kc++) {
        if (kc + 1 < NC) { CP_WAIT(1); } else { CP_WAIT(0); }
        __syncthreads();

        char* basep = smem + (size_t)(kc % 3) * SS;
        // convert x fp32 -> swizzled fp16 (thread t: row t>>2, 16B-dst-unit t&3)
        {
            int r = tid >> 2, c16 = tid & 3;
            float4 f0 = *reinterpret_cast<const float4*>(basep + OFF_X + (size_t)tid * 32);
            float4 f1 = *reinterpret_cast<const float4*>(basep + OFF_X + (size_t)tid * 32 + 16);
            uint4 hv;
            __half2 h0 = __floats2half2_rn(f0.x, f0.y);
            __half2 h1 = __floats2half2_rn(f0.z, f0.w);
            __half2 h2 = __floats2half2_rn(f1.x, f1.y);
            __half2 h3 = __floats2half2_rn(f1.z, f1.w);
            hv.x = *(uint32_t*)&h0; hv.y = *(uint32_t*)&h1;
            hv.z = *(uint32_t*)&h2; hv.w = *(uint32_t*)&h3;
            *reinterpret_cast<uint4*>(basep + OFF_A + swz(r, c16)) = hv;
        }
        __syncthreads();

        if (kc + 2 < NC) load_chunk(kc + 2);

        const uint32_t sA = sb + (uint32_t)(kc % 3) * SS + OFF_A;
        const uint32_t sB = sb + (uint32_t)(kc % 3) * SS + OFF_B;

        #pragma unroll
        for (int ks = 0; ks < 2; ks++) {
            uint32_t a[2][4];
            #pragma unroll
            for (int mt = 0; mt < 2; mt++) {
                int row = wm0 + mt * 16 + (lane & 15);
                int c16 = ks * 2 + (lane >> 4);
                LDSM_X4(a[mt], sA + swz(row, c16));
            }
            #pragma unroll
            for (int g = 0; g < 4; g++) {
                uint32_t b[4];
                int row = wn0 + g * 16 + (lane & 15);
                int c16 = ks * 2 + (lane >> 4);
                LDSM_X4(b, sB + swz(row, c16));
                #pragma unroll
                for (int mt = 0; mt < 2; mt++)
                    #pragma unroll
                    for (int h = 0; h < 2; h++)
                        mma16816h(acc[mt][g * 2 + h], a[mt], b[h], b[2 + h]);
            }
        }
        __syncthreads();
    }

    #pragma unroll
    for (int mt = 0; mt < 2; mt++) {
        int m = m0 + wm0 + mt * 16 + (lane >> 2);
        #pragma unroll
        for (int nt = 0; nt < 8; nt++) {
            int n = wn0 + nt * 8 + (lane & 3) * 2;
            if (m < Mrows)
                store2(C + (size_t)m * N_TOT + n, acc[mt][nt][0], acc[mt][nt][1]);
            if (m + 8 < Mrows)
                store2(C + (size_t)(m + 8) * N_TOT + n, acc[mt][nt][2], acc[mt][nt][3]);
        }
    }
}

// ---------------- fp16 GEMM via mma.sync, optional bias ----------------------------
// 256 threads, 8 warps (4m x 2n), warp tile 32 x BN/2; BK=32, 3-stage cp.async.
template<int BN, int K_TOT, int N_TOT, typename TOUT>
__global__ void __launch_bounds__(256, 1) gemm_fp16(
    const __half* __restrict__ A, const __half* __restrict__ B,
    const float* __restrict__ bias,
    TOUT* __restrict__ C, int Mrows)
{
    constexpr int NC = K_TOT / 32;
    constexpr int SS = 8192 + BN * 64;
    constexpr int NT16 = BN / 32;
    constexpr int NT8  = BN / 16;

    extern __shared__ __align__(128) char smem[];
    const uint32_t sb = smem_to_u32(smem);
    const int tid = threadIdx.x;
    const int wid = tid >> 5, lane = tid & 31;
    const int warpM = wid & 3, warpN = wid >> 2;
    const int m0 = blockIdx.x * 128;
    const int wm0 = warpM * 32;
    const int wn0 = warpN * (BN / 2);

    float acc[2][NT8][4];
    #pragma unroll
    for (int i = 0; i < 2; i++)
        #pragma unroll
        for (int j = 0; j < NT8; j++)
            #pragma unroll
            for (int q = 0; q < 4; q++) acc[i][j][q] = 0.f;

    auto load_chunk = [&](int kc) {
        const uint32_t sd = sb + (uint32_t)(kc % 3) * SS;
        #pragma unroll
        for (int i = tid; i < 512; i += 256) {
            int r = i >> 2, c16 = i & 3;
            uint32_t dst = sd + swz(r, c16);
            const char* g = (const char*)(A + (size_t)(m0 + r) * K_TOT) + kc * 64 + c16 * 16;
            CP_ASYNC16(dst, g);
        }
        #pragma unroll
        for (int i = tid; i < BN * 4; i += 256) {
            int r = i >> 2, c16 = i & 3;
            uint32_t dst = sd + 8192 + swz(r, c16);
            const char* g = (const char*)(B + (size_t)r * K_TOT) + kc * 64 + c16 * 16;
            CP_ASYNC16(dst, g);
        }
        CP_COMMIT();
    };

    load_chunk(0);
    if (NC > 1) load_chunk(1);

    for (int kc = 0; kc < NC; kc++) {
        if (kc + 1 < NC) { CP_WAIT(1); } else { CP_WAIT(0); }
        __syncthreads();
        if (kc + 2 < NC) load_chunk(kc + 2);

        const uint32_t sA = sb + (uint32_t)(kc % 3) * SS;
        const uint32_t sB = sA + 8192;

        #pragma unroll
        for (int ks = 0; ks < 2; ks++) {
            uint32_t a[2][4];
            #pragma unroll
            for (int mt = 0; mt < 2; mt++) {
                int row = wm0 + mt * 16 + (lane & 15);
                int c16 = ks * 2 + (lane >> 4);
                LDSM_X4(a[mt], sA + swz(row, c16));
            }
            #pragma unroll
            for (int g = 0; g < NT16; g++) {
                uint32_t b[4];
                int row = wn0 + g * 16 + (lane & 15);
                int c16 = ks * 2 + (lane >> 4);
                LDSM_X4(b, sB + swz(row, c16));
                #pragma unroll
                for (int mt = 0; mt < 2; mt++)
                    #pragma unroll
                    for (int h = 0; h < 2; h++)
                        mma16816h(acc[mt][g * 2 + h], a[mt], b[h], b[2 + h]);
            }
        }
        __syncthreads();
    }

    #pragma unroll
    for (int mt = 0; mt < 2; mt++) {
        int m = m0 + wm0 + mt * 16 + (lane >> 2);
        #pragma unroll
        for (int nt = 0; nt < NT8; nt++) {
            int n = wn0 + nt * 8 + (lane & 3) * 2;
            float bx = 0.f, by = 0.f;
            if (bias) {
                float2 bv = *reinterpret_cast<const float2*>(bias + n);
                bx = bv.x; by = bv.y;
            }
            if (m < Mrows)
                store2(C + (size_t)m * N_TOT + n, acc[mt][nt][0] + bx, acc[mt][nt][1] + by);
            if (m + 8 < Mrows)
                store2(C + (size_t)(m + 8) * N_TOT + n, acc[mt][nt][2] + bx, acc[mt][nt][3] + by);
        }
    }
}

// ---------------- SpMM over sorted CSR, fp16 gather -------------------------------
// spmm1: h = relu(spmm(adj, XW1h) + b1) -> fp16.  F=256: 32 threads/row.
template<int F>
__global__ void spmm1_fp16(const __half* __restrict__ src, const float* __restrict__ bias,
                           __half* __restrict__ dst, int nrows) {
    constexpr int TPR = F / 8;
    constexpr int RPB = 256 / TPR;
    const int lane = threadIdx.x % TPR;
    const int row  = blockIdx.x * RPB + threadIdx.x / TPR;
    if (row >= nrows) return;

    const int s = g_rowptr[row];
    const int e = g_rowptr[row + 1];
    float acc[8];
    #pragma unroll
    for (int q = 0; q < 8; q++) acc[q] = 0.f;

    const size_t loff = (size_t)lane * 8;
    for (int j = s; j < e; j++) {
        int2  ev = g_edges[j];
        float v  = __int_as_float(ev.y);
        uint4 r = *reinterpret_cast<const uint4*>(src + (size_t)ev.x * F + loff);
        float2 f0 = __half22float2(*reinterpret_cast<__half2*>(&r.x));
        float2 f1 = __half22float2(*reinterpret_cast<__half2*>(&r.y));
        float2 f2 = __half22float2(*reinterpret_cast<__half2*>(&r.z));
        float2 f3 = __half22float2(*reinterpret_cast<__half2*>(&r.w));
        acc[0] = fmaf(v, f0.x, acc[0]); acc[1] = fmaf(v, f0.y, acc[1]);
        acc[2] = fmaf(v, f1.x, acc[2]); acc[3] = fmaf(v, f1.y, acc[3]);
        acc[4] = fmaf(v, f2.x, acc[4]); acc[5] = fmaf(v, f2.y, acc[5]);
        acc[6] = fmaf(v, f3.x, acc[6]); acc[7] = fmaf(v, f3.y, acc[7]);
    }
    float4 b0 = *reinterpret_cast<const float4*>(bias + loff);
    float4 b1 = *reinterpret_cast<const float4*>(bias + loff + 4);
    acc[0] = fmaxf(acc[0] + b0.x, 0.f); acc[1] = fmaxf(acc[1] + b0.y, 0.f);
    acc[2] = fmaxf(acc[2] + b0.z, 0.f); acc[3] = fmaxf(acc[3] + b0.w, 0.f);
    acc[4] = fmaxf(acc[4] + b1.x, 0.f); acc[5] = fmaxf(acc[5] + b1.y, 0.f);
    acc[6] = fmaxf(acc[6] + b1.z, 0.f); acc[7] = fmaxf(acc[7] + b1.w, 0.f);

    uint4 hv;
    __half2 h0 = __floats2half2_rn(acc[0], acc[1]);
    __half2 h1 = __floats2half2_rn(acc[2], acc[3]);
    __half2 h2 = __floats2half2_rn(acc[4], acc[5]);
    __half2 h3 = __floats2half2_rn(acc[6], acc[7]);
    hv.x = *(uint32_t*)&h0; hv.y = *(uint32_t*)&h1;
    hv.z = *(uint32_t*)&h2; hv.w = *(uint32_t*)&h3;
    *reinterpret_cast<uint4*>(dst + (size_t)row * F + loff) = hv;
}

// spmm2: z = spmm(adj, HW2h) + b2 (fp32); zh = relu(z) fp16.  F=64: 8 threads/row.
template<int F>
__global__ void spmm2_k(const __half* __restrict__ src, const float* __restrict__ bias,
                        float* __restrict__ z, __half* __restrict__ zh, int nrows) {
    constexpr int TPR = F / 8;
    constexpr int RPB = 256 / TPR;
    const int lane = threadIdx.x % TPR;
    const int row  = blockIdx.x * RPB + threadIdx.x / TPR;
    if (row >= nrows) return;

    const int s = g_rowptr[row];
    const int e = g_rowptr[row + 1];
    float acc[8];
    #pragma unroll
    for (int q = 0; q < 8; q++) acc[q] = 0.f;

    const size_t loff = (size_t)lane * 8;
    for (int j = s; j < e; j++) {
        int2  ev = g_edges[j];
        float v  = __int_as_float(ev.y);
        uint4 r = *reinterpret_cast<const uint4*>(src + (size_t)ev.x * F + loff);
        float2 f0 = __half22float2(*reinterpret_cast<__half2*>(&r.x));
        float2 f1 = __half22float2(*reinterpret_cast<__half2*>(&r.y));
        float2 f2 = __half22float2(*reinterpret_cast<__half2*>(&r.z));
        float2 f3 = __half22float2(*reinterpret_cast<__half2*>(&r.w));
        acc[0] = fmaf(v, f0.x, acc[0]); acc[1] = fmaf(v, f0.y, acc[1]);
        acc[2] = fmaf(v, f1.x, acc[2]); acc[3] = fmaf(v, f1.y, acc[3]);
        acc[4] = fmaf(v, f2.x, acc[4]); acc[5] = fmaf(v, f2.y, acc[5]);
        acc[6] = fmaf(v, f3.x, acc[6]); acc[7] = fmaf(v, f3.y, acc[7]);
    }
    float4 b0 = *reinterpret_cast<const float4*>(bias + loff);
    float4 b1 = *reinterpret_cast<const float4*>(bias + loff + 4);
    acc[0] += b0.x; acc[1] += b0.y; acc[2] += b0.z; acc[3] += b0.w;
    acc[4] += b1.x; acc[5] += b1.y; acc[6] += b1.z; acc[7] += b1.w;

    size_t off = (size_t)row * F + loff;
    *reinterpret_cast<float4*>(z + off)     = make_float4(acc[0], acc[1], acc[2], acc[3]);
    *reinterpret_cast<float4*>(z + off + 4) = make_float4(acc[4], acc[5], acc[6], acc[7]);

    uint4 hv;
    __half2 h0 = __floats2half2_rn(fmaxf(acc[0], 0.f), fmaxf(acc[1], 0.f));
    __half2 h1 = __floats2half2_rn(fmaxf(acc[2], 0.f), fmaxf(acc[3], 0.f));
    __half2 h2 = __floats2half2_rn(fmaxf(acc[4], 0.f), fmaxf(acc[5], 0.f));
    __half2 h3 = __floats2half2_rn(fmaxf(acc[6], 0.f), fmaxf(acc[7], 0.f));
    hv.x = *(uint32_t*)&h0; hv.y = *(uint32_t*)&h1;
    hv.z = *(uint32_t*)&h2; hv.w = *(uint32_t*)&h3;
    *reinterpret_cast<uint4*>(zh + off) = hv;
}

// ---------------- log_softmax over 64 classes (warp per row) -----------------------
__global__ void k_logsoftmax(const float* __restrict__ z, float* __restrict__ out, int nrows) {
    int row  = blockIdx.x * 8 + threadIdx.x / 32;
    int lane = threadIdx.x & 31;
    if (row >= nrows) return;
    float2 v = *reinterpret_cast<const float2*>(z + (size_t)row * F_CLS + lane * 2);
    float m = fmaxf(v.x, v.y);
    #pragma unroll
    for (int off = 16; off; off >>= 1) m = fmaxf(m, __shfl_xor_sync(0xffffffffu, m, off));
    float s = expf(v.x - m) + expf(v.y - m);
    #pragma unroll
    for (int off = 16; off; off >>= 1) s += __shfl_xor_sync(0xffffffffu, s, off);
    float ls = m + logf(s);
    float2 o; o.x = v.x - ls; o.y = v.y - ls;
    *reinterpret_cast<float2*>(out + (size_t)row * F_CLS + lane * 2) = o;
}

// ---------------- launch ------------------------------------------------------------
static cudaStream_t s_side = nullptr;
static cudaEvent_t  s_evFork = nullptr, s_evJoin = nullptr;
static cudaEvent_t  s_evZ = nullptr, s_evLS = nullptr;

extern "C" void kernel_launch(void* const* d_in, const int* in_sizes, int n_in,
                              void* d_out, int out_size) {
    const float* x    = (const float*)d_in[0];
    const float* vals = (const float*)d_in[1];
    const float* W1   = (const float*)d_in[2];
    const float* b1   = (const float*)d_in[3];
    const float* W2   = (const float*)d_in[4];
    const float* b2   = (const float*)d_in[5];
    const float* W3   = (const float*)d_in[6];
    const float* b3   = (const float*)d_in[7];
    const int*   rows = (const int*)d_in[8];
    const int*   cols = (const int*)d_in[9];

    const int E = in_sizes[8];
    const int M = in_sizes[0] / F_IN;   // 100000

    float* out1 = (float*)d_out;                      // log_softmax [M, 64]
    float* out2 = (float*)d_out + (size_t)M * F_CLS;  // projection  [M, 128]

    float* pz;
    __half *pXW1h, *ph, *pHW2h, *pzh, *pw1t, *pw2t, *pw3t;
    cudaGetSymbolAddress((void**)&pXW1h, g_XW1h);
    cudaGetSymbolAddress((void**)&ph,    g_h);
    cudaGetSymbolAddress((void**)&pHW2h, g_HW2h);
    cudaGetSymbolAddress((void**)&pz,    g_z);
    cudaGetSymbolAddress((void**)&pzh,   g_zh);
    cudaGetSymbolAddress((void**)&pw1t,  g_w1t);
    cudaGetSymbolAddress((void**)&pw2t,  g_w2t);
    cudaGetSymbolAddress((void**)&pw3t,  g_w3t);

    if (s_side == nullptr) {
        cudaStreamCreateWithFlags(&s_side, cudaStreamNonBlocking);
        cudaEventCreateWithFlags(&s_evFork, cudaEventDisableTiming);
        cudaEventCreateWithFlags(&s_evJoin, cudaEventDisableTiming);
        cudaEventCreateWithFlags(&s_evZ,    cudaEventDisableTiming);
        cudaEventCreateWithFlags(&s_evLS,   cudaEventDisableTiming);
    }

    constexpr int SMEM1 = 3 * 40960;               // gemm1_fused: 122880
    constexpr int SMEM2 = 3 * (8192 + 64 * 64);    // gemm2: 36864
    constexpr int SMEM3 = 3 * (8192 + 128 * 64);   // gemm3: 49152
    cudaFuncSetAttribute(gemm1_fused, cudaFuncAttributeMaxDynamicSharedMemorySize, SMEM1);
    cudaFuncSetAttribute(gemm_fp16<64, F_HID, F_CLS, __half>,
                         cudaFuncAttributeMaxDynamicSharedMemorySize, SMEM2);
    cudaFuncSetAttribute(gemm_fp16<128, F_CLS, F_PROJ, float>,
                         cudaFuncAttributeMaxDynamicSharedMemorySize, SMEM3);

    const int MT = NN_PAD / 128;  // 782 row tiles

    // ---- fork: CSR build on side stream, concurrent with GEMM1 path ---------------
    cudaEventRecord(s_evFork, 0);
    cudaStreamWaitEvent(s_side, s_evFork, 0);

    k_zero_counts<<<(M + 255) / 256, 256, 0, s_side>>>(M);
    k_hist<<<(E + 1023) / 1024, 256, 0, s_side>>>(rows, E);
    k_scan<<<1, 1024, 0, s_side>>>(M);
    k_scatter<<<(E + 1023) / 1024, 256, 0, s_side>>>(rows, cols, vals, E);
    cudaEventRecord(s_evJoin, s_side);

    // ---- main stream: weight prep + GEMM1 ------------------------------------------
    k_transpose_h<<<(F_IN * F_HID + 255) / 256, 256>>>(W1, pw1t, F_IN, F_HID);
    k_transpose_h<<<(F_HID * F_CLS + 255) / 256, 256>>>(W2, pw2t, F_HID, F_CLS);
    k_transpose_h<<<(F_CLS * F_PROJ + 255) / 256, 256>>>(W3, pw3t, F_CLS, F_PROJ);

    gemm1_fused<<<MT, 512, SMEM1>>>(x, pw1t, pXW1h, M);

    // ---- join: SpMM1 needs both CSR and XW1 -----------------------------------------
    cudaStreamWaitEvent(0, s_evJoin, 0);

    spmm1_fp16<F_HID><<<(M + 7) / 8, 256>>>(pXW1h, b1, ph, M);

    gemm_fp16<64, F_HID, F_CLS, __half><<<dim3(MT, 1), 256, SMEM2>>>(
        ph, pw2t, nullptr, pHW2h, M);

    spmm2_k<F_CLS><<<(M + 31) / 32, 256>>>(pHW2h, b2, pz, pzh, M);

    // ---- fork 2: log_softmax (out1) on side, concurrent with GEMM3 (out2) -----------
    cudaEventRecord(s_evZ, 0);
    cudaStreamWaitEvent(s_side, s_evZ, 0);
    k_logsoftmax<<<(M + 7) / 8, 256, 0, s_side>>>(pz, out1, M);
    cudaEventRecord(s_evLS, s_side);

    gemm_fp16<128, F_CLS, F_PROJ, float><<<dim3(MT, 1), 256, SMEM3>>>(
        pzh, pw3t, b3, out2, M);

    cudaStreamWaitEvent(0, s_evLS, 0);
}